// round 11
// baseline (speedup 1.0000x reference)
#include <cuda_runtime.h>
#include <cuda_fp16.h>
#include <math.h>

#define MAXN 16384
#define MAXE 524288
#define NTAB 4096
#define RMAXF 5.0f
#define NLAYERS 3
#define ENT 16
#define JT 16

// ---------------- static scratch (no allocation allowed) ----------------
__device__ uint4     g_ev[MAXE];        // unsorted: {yx h2, yy h2, yz h2, (src<<12)|i0}
__device__ uint4     g_rec[MAXE];       // dst-sorted records (same format)
__device__ int       g_hist[MAXN];      // zeroed by k_scatter for next replay
__device__ int       g_cur[MAXN];
__device__ int       g_off[MAXN + 1];
// nearest-entry half tables per lane: vals paths1-4 (16B), val path5 (4B)
__device__ uint4     g_tV[NLAYERS * NTAB * 32];
__device__ unsigned  g_t5[NLAYERS * NTAB * 32];
__device__ float     g_s[MAXN * 64];
__device__ float     g_v[MAXN * 192];   // layout [n][3][64]
__device__ float     g_as[MAXN * 64];
__device__ float     g_av[MAXN * 192];
__device__ uint4     g_feat[MAXN * 32]; // per lane: {s h2, vx h2, vy h2, vz h2}

// ================= mega kernel: edge_pre | table build | init =================
__global__ void k_mega(const float* __restrict__ pos,
                       const int* __restrict__ esrc,
                       const int* __restrict__ edst,
                       const float* __restrict__ shift,
                       const float* __restrict__ cell,
                       const int* __restrict__ img,
                       const int* __restrict__ atom_type,
                       const float* __restrict__ w_lin_in,
                       const float* __restrict__ mw1,
                       const float* __restrict__ mb1,
                       const float* __restrict__ mw2,
                       int E, int N, int nEdgeBlk, int nTabBlk) {
    __shared__ float sh_h[ENT * 64];   // 4KB  (table branch)
    __shared__ float sh_w[JT * 320];   // 20KB (table branch)
    int b = blockIdx.x;
    int tid = threadIdx.x;

    if (b < nEdgeBlk) {
        // ---- edge preprocess ----
        int e = b * 256 + tid;
        if (e >= E) return;
        int s = esrc[e], d = edst[e];
        float vx = pos[d * 3 + 0] - pos[s * 3 + 0];
        float vy = pos[d * 3 + 1] - pos[s * 3 + 1];
        float vz = pos[d * 3 + 2] - pos[s * 3 + 2];
        float s0 = shift[e * 3 + 0], s1 = shift[e * 3 + 1], s2 = shift[e * 3 + 2];
        const float* Cm = cell + img[s] * 9;
        vx += s0 * Cm[0] + s1 * Cm[3] + s2 * Cm[6];
        vy += s0 * Cm[1] + s1 * Cm[4] + s2 * Cm[7];
        vz += s0 * Cm[2] + s1 * Cm[5] + s2 * Cm[8];
        float r = sqrtf(vx * vx + vy * vy + vz * vz);
        uint4 rec;
        if (r < RMAXF) {
            float inv = 1.7320508075688772f / fmaxf(r, 1e-9f);  // sqrt3 * unit
            __half2 hx = __half2half2(__float2half_rn(vx * inv));
            __half2 hy = __half2half2(__float2half_rn(vy * inv));
            __half2 hz = __half2half2(__float2half_rn(vz * inv));
            int i0 = __float2int_rn(r * ((float)(NTAB - 1) / RMAXF));
            if (i0 > NTAB - 1) i0 = NTAB - 1;
            rec.x = *(unsigned*)&hx; rec.y = *(unsigned*)&hy;
            rec.z = *(unsigned*)&hz;
            rec.w = ((unsigned)s << 12) | (unsigned)i0;
            atomicAdd(&g_hist[d], 1);
        } else {
            rec.x = rec.y = rec.z = 0;
            rec.w = 0xFFFFFFFFu;   // filtered marker
        }
        g_ev[e] = rec;
    } else if (b < nEdgeBlk + nTabBlk) {
        // ---- fused table build: h in-block, GEMM, pack ----
        int tb = b - nEdgeBlk;
        int L = tb / (NTAB / ENT);
        int e_blk = (tb % (NTAB / ENT)) * ENT;
        for (int i = tid; i < ENT * 64; i += 256) {
            int el = i >> 6, t = i & 63;
            int entry = e_blk + el;
            float r = (float)entry * (RMAXF / (float)(NTAB - 1));
            float rs = fmaxf(r, 1e-9f);
            float x = r / RMAXF;
            float x2 = x * x;
            float x6 = x2 * x2 * x2;
            float fc = 1.f - 28.f * x6 + 48.f * x6 * x - 21.f * x6 * x2;
            if (x >= 1.f) fc = 0.f;
            float cscale = sqrtf(2.f / RMAXF) * fc / rs;
            float arg = 3.14159265358979323846f * rs / RMAXF;
            float h = mb1[L * 64 + t];
#pragma unroll
            for (int j = 0; j < 8; j++)
                h += cscale * sinf((float)(j + 1) * arg) * mw1[(L * 8 + j) * 64 + t];
            sh_h[i] = h / (1.f + expf(-h));  // silu
        }

        int c = tid & 63;
        int eg = tid >> 6;
        float acc[4][5];
#pragma unroll
        for (int q = 0; q < 4; q++)
#pragma unroll
            for (int k = 0; k < 5; k++) acc[q][k] = 0.f;

        for (int j0 = 0; j0 < 64; j0 += JT) {
            __syncthreads();
            const float* wsrc = mw2 + ((size_t)L * 64 + j0) * 320;
            for (int i = tid; i < JT * 320; i += 256) sh_w[i] = wsrc[i];
            __syncthreads();
#pragma unroll
            for (int j = 0; j < JT; j++) {
                float w0 = sh_w[j * 320 + 0 * 64 + c];
                float w1 = sh_w[j * 320 + 1 * 64 + c];
                float w2 = sh_w[j * 320 + 2 * 64 + c];
                float w3 = sh_w[j * 320 + 3 * 64 + c];
                float w4 = sh_w[j * 320 + 4 * 64 + c];
#pragma unroll
                for (int q = 0; q < 4; q++) {
                    float hj = sh_h[(eg * 4 + q) * 64 + j0 + j];
                    acc[q][0] += hj * w0;
                    acc[q][1] += hj * w1;
                    acc[q][2] += hj * w2;
                    acc[q][3] += hj * w3;
                    acc[q][4] += hj * w4;
                }
            }
        }
        const float ISD = 0.17677669529663687f;          // 1/sqrt(32)
        const float SC[5] = {ISD, ISD * 0.57735026918962576f, ISD, ISD,
                             ISD * 0.70710678118654752f};
        __syncthreads();
#pragma unroll
        for (int q = 0; q < 4; q++)
#pragma unroll
            for (int k = 0; k < 5; k++)
                sh_w[(eg * 4 + q) * 320 + k * 64 + c] = acc[q][k] * SC[k];
        __syncthreads();
        for (int u = tid; u < ENT * 32; u += 256) {
            int el = u >> 5, lane = u & 31, cc = lane * 2;
            const float* row = sh_w + el * 320;
            __half2 p1 = __floats2half2_rn(row[0 * 64 + cc], row[0 * 64 + cc + 1]);
            __half2 p2 = __floats2half2_rn(row[1 * 64 + cc], row[1 * 64 + cc + 1]);
            __half2 p3 = __floats2half2_rn(row[2 * 64 + cc], row[2 * 64 + cc + 1]);
            __half2 p4 = __floats2half2_rn(row[3 * 64 + cc], row[3 * 64 + cc + 1]);
            __half2 p5 = __floats2half2_rn(row[4 * 64 + cc], row[4 * 64 + cc + 1]);
            size_t base = ((size_t)L * NTAB + e_blk + el) * 32 + lane;
            g_tV[base] = make_uint4(*(unsigned*)&p1, *(unsigned*)&p2,
                                    *(unsigned*)&p3, *(unsigned*)&p4);
            g_t5[base] = *(unsigned*)&p5;
        }
    } else {
        // ---- node feature init ----
        int i = (b - nEdgeBlk - nTabBlk) * 256 + tid;
        if (i < N * 192) g_v[i] = 0.f;
        if (i < N * 64) {
            int n = i >> 6, cc = i & 63;
            g_s[i] = w_lin_in[atom_type[n] * 64 + cc];
        }
        if (i < N * 32) {
            int n = i >> 5, l = i & 31;
            int t = atom_type[n];
            __half2 s2 = __floats2half2_rn(w_lin_in[t * 64 + 2 * l],
                                           w_lin_in[t * 64 + 2 * l + 1]);
            __half2 z2 = __floats2half2_rn(0.f, 0.f);
            uint4 f4;
            f4.x = *(unsigned*)&s2; f4.y = *(unsigned*)&z2;
            f4.z = *(unsigned*)&z2; f4.w = *(unsigned*)&z2;
            g_feat[i] = f4;
        }
    }
}

// ---------------- single-block exclusive scan ----------------
__global__ void k_scan(int N) {
    __shared__ int sm[1024];
    int tid = threadIdx.x;
    int per = (N + 1023) >> 10;
    int st = tid * per;
    int s = 0;
    for (int i = 0; i < per; i++) { int idx = st + i; if (idx < N) s += g_hist[idx]; }
    sm[tid] = s;
    __syncthreads();
    for (int d = 1; d < 1024; d <<= 1) {
        int v = (tid >= d) ? sm[tid - d] : 0;
        __syncthreads();
        sm[tid] += v;
        __syncthreads();
    }
    int pre = tid ? sm[tid - 1] : 0;
    for (int i = 0; i < per; i++) {
        int idx = st + i;
        if (idx < N) { g_off[idx] = pre; g_cur[idx] = pre; pre += g_hist[idx]; }
    }
    if (tid == 0) g_off[N] = sm[1023];
}

// -------- scatter into dst-sorted order; also re-zero g_hist for next replay --------
__global__ void k_scatter(const int* __restrict__ edst, int E, int N) {
    int e = blockIdx.x * blockDim.x + threadIdx.x;
    if (e < N) g_hist[e] = 0;
    if (e >= E) return;
    uint4 rec = g_ev[e];
    if (rec.w == 0xFFFFFFFFu) return;   // filtered
    int d = edst[e];
    int p = atomicAdd(&g_cur[d], 1);
    g_rec[p] = rec;
}

#define H2(u) (*(__half2*)&(u))

// per-edge message math in half2; accumulates into 4 half2 accumulators
__device__ __forceinline__ void edge_msg(uint4 rc, uint4 qv, unsigned q5, uint4 ft,
                                         __half2& hS, __half2& hX,
                                         __half2& hY, __half2& hZ) {
    __half2 w1 = H2(qv.x), w2 = H2(qv.y), w3 = H2(qv.z), w4 = H2(qv.w), w5 = H2(q5);
    __half2 s01 = H2(ft.x), vx = H2(ft.y), vy = H2(ft.z), vz = H2(ft.w);
    __half2 yx2 = H2(rc.x), yy2 = H2(rc.y), yz2 = H2(rc.z);
    __half2 vd = __hfma2(vz, yz2, __hfma2(vy, yy2, __hmul2(vx, yx2)));
    hS = __hadd2(hS, __hfma2(w2, vd, __hmul2(w1, s01)));
    __half2 t3 = __hmul2(w3, s01);
    __half2 nvx = __hneg2(vx), nvy = __hneg2(vy), nvz = __hneg2(vz);
    __half2 cxh = __hfma2(nvz, yy2, __hmul2(vy, yz2));
    __half2 cyh = __hfma2(nvx, yz2, __hmul2(vz, yx2));
    __half2 czh = __hfma2(nvy, yx2, __hmul2(vx, yy2));
    hX = __hadd2(hX, __hfma2(w5, cxh, __hfma2(w4, vx, __hmul2(t3, yx2))));
    hY = __hadd2(hY, __hfma2(w5, cyh, __hfma2(w4, vy, __hmul2(t3, yy2))));
    hZ = __hadd2(hZ, __hfma2(w5, czh, __hfma2(w4, vz, __hmul2(t3, yz2))));
}

// ------- main per-layer aggregate: TWO warps per dst atom (even/odd edges),
//         chunk-of-4 unrolled body, half2 math, fp32 flush per chunk -------
__global__ void k_aggregate(int L, int N) {
    __shared__ float red[4][8][32];
    int tid = threadIdx.x;
    int lane = tid & 31;
    int warpInBlk = tid >> 5;
    int atomInBlk = warpInBlk >> 1;
    int half = warpInBlk & 1;
    int atom = blockIdx.x * 4 + atomInBlk;
    int valid = atom < N;
    int o0 = valid ? g_off[atom] : 0;
    int o1 = valid ? g_off[atom + 1] : 0;
    int c0 = lane << 1;
    float aS0 = 0, aS1 = 0, aX0 = 0, aX1 = 0, aY0 = 0, aY1 = 0, aZ0 = 0, aZ1 = 0;
    const uint4* tV = g_tV + (size_t)L * NTAB * 32;
    const unsigned* t5 = g_t5 + (size_t)L * NTAB * 32;
    const __half2 hz2 = __floats2half2_rn(0.f, 0.f);

    int p = o0 + half;
    // chunks of 4 edges at stride 2 (indices p, p+2, p+4, p+6)
    for (; p + 6 < o1; p += 8) {
        __half2 hS = hz2, hX = hz2, hY = hz2, hZ = hz2;
#pragma unroll
        for (int u = 0; u < 4; u++) {
            uint4 rc = g_rec[p + 2 * u];
            int ib = (int)(rc.w & 0xFFFu) * 32 + lane;
            int src = (int)(rc.w >> 12);
            uint4 qv = tV[ib];
            unsigned q5 = t5[ib];
            uint4 ft = g_feat[src * 32 + lane];
            edge_msg(rc, qv, q5, ft, hS, hX, hY, hZ);
        }
        float2 f;
        f = __half22float2(hS); aS0 += f.x; aS1 += f.y;
        f = __half22float2(hX); aX0 += f.x; aX1 += f.y;
        f = __half22float2(hY); aY0 += f.x; aY1 += f.y;
        f = __half22float2(hZ); aZ0 += f.x; aZ1 += f.y;
    }
    // tail: direct fp32 accumulation
    for (; p < o1; p += 2) {
        uint4 rc = g_rec[p];
        int ib = (int)(rc.w & 0xFFFu) * 32 + lane;
        int src = (int)(rc.w >> 12);
        uint4 qv = tV[ib];
        unsigned q5 = t5[ib];
        uint4 ft = g_feat[src * 32 + lane];
        __half2 hS = hz2, hX = hz2, hY = hz2, hZ = hz2;
        edge_msg(rc, qv, q5, ft, hS, hX, hY, hZ);
        float2 f;
        f = __half22float2(hS); aS0 += f.x; aS1 += f.y;
        f = __half22float2(hX); aX0 += f.x; aX1 += f.y;
        f = __half22float2(hY); aY0 += f.x; aY1 += f.y;
        f = __half22float2(hZ); aZ0 += f.x; aZ1 += f.y;
    }

    // cross-warp reduction (odd half -> smem, even half combines & writes)
    if (half) {
        red[atomInBlk][0][lane] = aS0; red[atomInBlk][1][lane] = aS1;
        red[atomInBlk][2][lane] = aX0; red[atomInBlk][3][lane] = aX1;
        red[atomInBlk][4][lane] = aY0; red[atomInBlk][5][lane] = aY1;
        red[atomInBlk][6][lane] = aZ0; red[atomInBlk][7][lane] = aZ1;
    }
    __syncthreads();
    if (!half && valid) {
        aS0 += red[atomInBlk][0][lane]; aS1 += red[atomInBlk][1][lane];
        aX0 += red[atomInBlk][2][lane]; aX1 += red[atomInBlk][3][lane];
        aY0 += red[atomInBlk][4][lane]; aY1 += red[atomInBlk][5][lane];
        aZ0 += red[atomInBlk][6][lane]; aZ1 += red[atomInBlk][7][lane];
        *(float2*)(g_as + atom * 64 + c0) = make_float2(aS0, aS1);
        float* ov = g_av + atom * 192 + c0;
        *(float2*)(ov) = make_float2(aX0, aX1);
        *(float2*)(ov + 64) = make_float2(aY0, aY1);
        *(float2*)(ov + 128) = make_float2(aZ0, aZ1);
    }
}

// ---- node self-interaction + resnet (+feat mirror); 4 atoms per warp ----
__global__ void k_node(int L, int N, const float* __restrict__ wss,
                       const float* __restrict__ wsv,
                       const float* __restrict__ wgt) {
    __shared__ float sWs[4096];
    __shared__ float sWv[4096];
    __shared__ float sWg[4096];
    const float* ps = wss + (size_t)L * 4096;
    const float* pv = wsv + (size_t)L * 4096;
    const float* pg = wgt + (size_t)L * 4096;
    for (int i = threadIdx.x; i < 4096; i += blockDim.x) {
        sWs[i] = ps[i]; sWv[i] = pv[i]; sWg[i] = pg[i];
    }
    __syncthreads();
    int lane = threadIdx.x & 31;
    int c0 = lane << 1;
    int baseAtom = blockIdx.x * 32 + (threadIdx.x >> 5) * 4;
    for (int a = 0; a < 4; a++) {
        int gw = baseAtom + a;
        if (gw >= N) break;
        float2 aa = *(const float2*)(g_as + gw * 64 + c0);
        const float* avp = g_av + gw * 192 + c0;
        float2 ax = *(const float2*)(avp);
        float2 ay = *(const float2*)(avp + 64);
        float2 az = *(const float2*)(avp + 128);
        float gs0 = 0, gs1 = 0, t0 = 0, t1 = 0;
        float vx0 = 0, vx1 = 0, vy0 = 0, vy1 = 0, vz0 = 0, vz1 = 0;
#pragma unroll
        for (int j = 0; j < 64; j++) {
            int sl = j >> 1;
            float aj = __shfl_sync(0xffffffffu, (j & 1) ? aa.y : aa.x, sl);
            float jx = __shfl_sync(0xffffffffu, (j & 1) ? ax.y : ax.x, sl);
            float jy = __shfl_sync(0xffffffffu, (j & 1) ? ay.y : ay.x, sl);
            float jz = __shfl_sync(0xffffffffu, (j & 1) ? az.y : az.x, sl);
            float2 wg2 = *(const float2*)(sWg + j * 64 + c0);
            float2 ws2 = *(const float2*)(sWs + j * 64 + c0);
            float2 wv2 = *(const float2*)(sWv + j * 64 + c0);
            gs0 += aj * wg2.x; gs1 += aj * wg2.y;
            t0 += aj * ws2.x;  t1 += aj * ws2.y;
            vx0 += jx * wv2.x; vx1 += jx * wv2.y;
            vy0 += jy * wv2.x; vy1 += jy * wv2.y;
            vz0 += jz * wv2.x; vz1 += jz * wv2.y;
        }
        float g0 = 1.f / (1.f + expf(-gs0));
        float g1 = 1.f / (1.f + expf(-gs1));
        float si0 = t0 / (1.f + expf(-t0));
        float si1 = t1 / (1.f + expf(-t1));
        float* sp = g_s + gw * 64 + c0;
        float2 sv = *(float2*)sp;
        sv.x += si0; sv.y += si1;
        *(float2*)sp = sv;
        float* vp = g_v + gw * 192 + c0;
        float2 v1, v2, v3;
        v1 = *(float2*)(vp);       v1.x += vx0 * g0; v1.y += vx1 * g1; *(float2*)(vp) = v1;
        v2 = *(float2*)(vp + 64);  v2.x += vy0 * g0; v2.y += vy1 * g1; *(float2*)(vp + 64) = v2;
        v3 = *(float2*)(vp + 128); v3.x += vz0 * g0; v3.y += vz1 * g1; *(float2*)(vp + 128) = v3;
        __half2 hs = __floats2half2_rn(sv.x, sv.y);
        __half2 h1 = __floats2half2_rn(v1.x, v1.y);
        __half2 h2 = __floats2half2_rn(v2.x, v2.y);
        __half2 h3 = __floats2half2_rn(v3.x, v3.y);
        uint4 f4;
        f4.x = *(unsigned*)&hs; f4.y = *(unsigned*)&h1;
        f4.z = *(unsigned*)&h2; f4.w = *(unsigned*)&h3;
        g_feat[gw * 32 + lane] = f4;
    }
}

// ---------------- final energy head ----------------
__global__ void k_energy(int N, const float* __restrict__ wl1,
                         const float* __restrict__ wl2,
                         float* __restrict__ out) {
    __shared__ float sW[1024];
    __shared__ float sw2[16];
    for (int i = threadIdx.x; i < 1024; i += blockDim.x) sW[i] = wl1[i];
    if (threadIdx.x < 16) sw2[threadIdx.x] = wl2[threadIdx.x];
    __syncthreads();
    int gw = blockIdx.x * 8 + (threadIdx.x >> 5);
    if (gw >= N) return;
    int lane = threadIdx.x & 31;
    int c0 = lane << 1;
    float2 s = *(const float2*)(g_s + gw * 64 + c0);
    float p[16];
#pragma unroll
    for (int k = 0; k < 16; k++)
        p[k] = s.x * sW[c0 * 16 + k] + s.y * sW[(c0 + 1) * 16 + k];
#pragma unroll
    for (int d = 16; d >= 1; d >>= 1) {
#pragma unroll
        for (int k = 0; k < 16; k++) p[k] += __shfl_down_sync(0xffffffffu, p[k], d);
    }
    if (lane == 0) {
        float e = 0.f;
#pragma unroll
        for (int k = 0; k < 16; k++) e += p[k] * sw2[k];
        out[gw] = e;
    }
}

// ---------------- launch ----------------
extern "C" void kernel_launch(void* const* d_in, const int* in_sizes, int n_in,
                              void* d_out, int out_size) {
    const int*   atom_type = (const int*)d_in[0];
    const float* atom_pos  = (const float*)d_in[1];
    const int*   edge_src  = (const int*)d_in[2];
    const int*   edge_dst  = (const int*)d_in[3];
    const float* shift     = (const float*)d_in[4];
    const float* cell      = (const float*)d_in[5];
    const int*   image_idx = (const int*)d_in[6];
    const float* w_lin_in  = (const float*)d_in[7];
    const float* mw1       = (const float*)d_in[8];
    const float* mb1       = (const float*)d_in[9];
    const float* mw2       = (const float*)d_in[10];
    const float* wss       = (const float*)d_in[11];
    const float* wsv       = (const float*)d_in[12];
    const float* wgt       = (const float*)d_in[13];
    const float* wl1       = (const float*)d_in[14];
    const float* wl2       = (const float*)d_in[15];
    int N = in_sizes[0];
    int E = in_sizes[2];
    float* out = (float*)d_out;

    int nEdgeBlk = (E + 255) / 256;
    int nTabBlk  = NLAYERS * (NTAB / ENT);
    int nInitBlk = (N * 192 + 255) / 256;

    k_mega<<<nEdgeBlk + nTabBlk + nInitBlk, 256>>>(
        atom_pos, edge_src, edge_dst, shift, cell, image_idx,
        atom_type, w_lin_in, mw1, mb1, mw2, E, N, nEdgeBlk, nTabBlk);
    k_scan<<<1, 1024>>>(N);
    k_scatter<<<(E + 255) / 256, 256>>>(edge_dst, E, N);
    for (int L = 0; L < NLAYERS; ++L) {
        k_aggregate<<<(N + 3) / 4, 256>>>(L, N);
        k_node<<<(N + 31) / 32, 256>>>(L, N, wss, wsv, wgt);
    }
    k_energy<<<(N + 7) / 8, 256>>>(N, wl1, wl2, out);
}

// round 12
// speedup vs baseline: 1.0310x; 1.0310x over previous
#include <cuda_runtime.h>
#include <cuda_fp16.h>
#include <math.h>

#define MAXN 16384
#define MAXE 524288
#define NTAB 4096
#define RMAXF 5.0f
#define NLAYERS 3
#define ENT 16
#define JT 16

// ---------------- static scratch (no allocation allowed) ----------------
__device__ uint4     g_ev[MAXE];        // unsorted: {yx h2, yy h2, yz h2, (src<<12)|i0}
__device__ uint4     g_rec[MAXE];       // dst-sorted records (same format)
__device__ int       g_hist[MAXN];      // zeroed by k_scatter for next replay
__device__ int       g_cur[MAXN];
__device__ int       g_off[MAXN + 1];
// nearest-entry half tables per lane: vals paths1-4 (16B), val path5 (4B)
__device__ uint4     g_tV[NLAYERS * NTAB * 32];
__device__ unsigned  g_t5[NLAYERS * NTAB * 32];
__device__ float     g_s[MAXN * 64];
__device__ float     g_v[MAXN * 192];   // layout [n][3][64]
__device__ float     g_as[MAXN * 64];
__device__ float     g_av[MAXN * 192];
__device__ uint4     g_feat[MAXN * 32]; // per lane: {s h2, vx h2, vy h2, vz h2}

// ================= mega kernel: edge_pre | table build | init =================
__global__ void k_mega(const float* __restrict__ pos,
                       const int* __restrict__ esrc,
                       const int* __restrict__ edst,
                       const float* __restrict__ shift,
                       const float* __restrict__ cell,
                       const int* __restrict__ img,
                       const int* __restrict__ atom_type,
                       const float* __restrict__ w_lin_in,
                       const float* __restrict__ mw1,
                       const float* __restrict__ mb1,
                       const float* __restrict__ mw2,
                       int E, int N, int nEdgeBlk, int nTabBlk) {
    __shared__ float sh_h[ENT * 64];   // 4KB  (table branch)
    __shared__ float sh_w[JT * 320];   // 20KB (table branch)
    int b = blockIdx.x;
    int tid = threadIdx.x;

    if (b < nEdgeBlk) {
        // ---- edge preprocess ----
        int e = b * 256 + tid;
        if (e >= E) return;
        int s = esrc[e], d = edst[e];
        float vx = pos[d * 3 + 0] - pos[s * 3 + 0];
        float vy = pos[d * 3 + 1] - pos[s * 3 + 1];
        float vz = pos[d * 3 + 2] - pos[s * 3 + 2];
        float s0 = shift[e * 3 + 0], s1 = shift[e * 3 + 1], s2 = shift[e * 3 + 2];
        const float* Cm = cell + img[s] * 9;
        vx += s0 * Cm[0] + s1 * Cm[3] + s2 * Cm[6];
        vy += s0 * Cm[1] + s1 * Cm[4] + s2 * Cm[7];
        vz += s0 * Cm[2] + s1 * Cm[5] + s2 * Cm[8];
        float r = sqrtf(vx * vx + vy * vy + vz * vz);
        uint4 rec;
        if (r < RMAXF) {
            float inv = 1.7320508075688772f / fmaxf(r, 1e-9f);  // sqrt3 * unit
            __half2 hx = __half2half2(__float2half_rn(vx * inv));
            __half2 hy = __half2half2(__float2half_rn(vy * inv));
            __half2 hz = __half2half2(__float2half_rn(vz * inv));
            int i0 = __float2int_rn(r * ((float)(NTAB - 1) / RMAXF));
            if (i0 > NTAB - 1) i0 = NTAB - 1;
            rec.x = *(unsigned*)&hx; rec.y = *(unsigned*)&hy;
            rec.z = *(unsigned*)&hz;
            rec.w = ((unsigned)s << 12) | (unsigned)i0;
            atomicAdd(&g_hist[d], 1);
        } else {
            rec.x = rec.y = rec.z = 0;
            rec.w = 0xFFFFFFFFu;   // filtered marker
        }
        g_ev[e] = rec;
    } else if (b < nEdgeBlk + nTabBlk) {
        // ---- fused table build: h in-block, GEMM, pack ----
        int tb = b - nEdgeBlk;
        int L = tb / (NTAB / ENT);
        int e_blk = (tb % (NTAB / ENT)) * ENT;
        for (int i = tid; i < ENT * 64; i += 256) {
            int el = i >> 6, t = i & 63;
            int entry = e_blk + el;
            float r = (float)entry * (RMAXF / (float)(NTAB - 1));
            float rs = fmaxf(r, 1e-9f);
            float x = r / RMAXF;
            float x2 = x * x;
            float x6 = x2 * x2 * x2;
            float fc = 1.f - 28.f * x6 + 48.f * x6 * x - 21.f * x6 * x2;
            if (x >= 1.f) fc = 0.f;
            float cscale = sqrtf(2.f / RMAXF) * fc / rs;
            float arg = 3.14159265358979323846f * rs / RMAXF;
            float h = mb1[L * 64 + t];
#pragma unroll
            for (int j = 0; j < 8; j++)
                h += cscale * sinf((float)(j + 1) * arg) * mw1[(L * 8 + j) * 64 + t];
            sh_h[i] = h / (1.f + expf(-h));  // silu
        }

        int c = tid & 63;
        int eg = tid >> 6;
        float acc[4][5];
#pragma unroll
        for (int q = 0; q < 4; q++)
#pragma unroll
            for (int k = 0; k < 5; k++) acc[q][k] = 0.f;

        for (int j0 = 0; j0 < 64; j0 += JT) {
            __syncthreads();
            const float* wsrc = mw2 + ((size_t)L * 64 + j0) * 320;
            for (int i = tid; i < JT * 320; i += 256) sh_w[i] = wsrc[i];
            __syncthreads();
#pragma unroll
            for (int j = 0; j < JT; j++) {
                float w0 = sh_w[j * 320 + 0 * 64 + c];
                float w1 = sh_w[j * 320 + 1 * 64 + c];
                float w2 = sh_w[j * 320 + 2 * 64 + c];
                float w3 = sh_w[j * 320 + 3 * 64 + c];
                float w4 = sh_w[j * 320 + 4 * 64 + c];
#pragma unroll
                for (int q = 0; q < 4; q++) {
                    float hj = sh_h[(eg * 4 + q) * 64 + j0 + j];
                    acc[q][0] += hj * w0;
                    acc[q][1] += hj * w1;
                    acc[q][2] += hj * w2;
                    acc[q][3] += hj * w3;
                    acc[q][4] += hj * w4;
                }
            }
        }
        const float ISD = 0.17677669529663687f;          // 1/sqrt(32)
        const float SC[5] = {ISD, ISD * 0.57735026918962576f, ISD, ISD,
                             ISD * 0.70710678118654752f};
        __syncthreads();
#pragma unroll
        for (int q = 0; q < 4; q++)
#pragma unroll
            for (int k = 0; k < 5; k++)
                sh_w[(eg * 4 + q) * 320 + k * 64 + c] = acc[q][k] * SC[k];
        __syncthreads();
        for (int u = tid; u < ENT * 32; u += 256) {
            int el = u >> 5, lane = u & 31, cc = lane * 2;
            const float* row = sh_w + el * 320;
            __half2 p1 = __floats2half2_rn(row[0 * 64 + cc], row[0 * 64 + cc + 1]);
            __half2 p2 = __floats2half2_rn(row[1 * 64 + cc], row[1 * 64 + cc + 1]);
            __half2 p3 = __floats2half2_rn(row[2 * 64 + cc], row[2 * 64 + cc + 1]);
            __half2 p4 = __floats2half2_rn(row[3 * 64 + cc], row[3 * 64 + cc + 1]);
            __half2 p5 = __floats2half2_rn(row[4 * 64 + cc], row[4 * 64 + cc + 1]);
            size_t base = ((size_t)L * NTAB + e_blk + el) * 32 + lane;
            g_tV[base] = make_uint4(*(unsigned*)&p1, *(unsigned*)&p2,
                                    *(unsigned*)&p3, *(unsigned*)&p4);
            g_t5[base] = *(unsigned*)&p5;
        }
    } else {
        // ---- node feature init ----
        int i = (b - nEdgeBlk - nTabBlk) * 256 + tid;
        if (i < N * 192) g_v[i] = 0.f;
        if (i < N * 64) {
            int n = i >> 6, cc = i & 63;
            g_s[i] = w_lin_in[atom_type[n] * 64 + cc];
        }
        if (i < N * 32) {
            int n = i >> 5, l = i & 31;
            int t = atom_type[n];
            __half2 s2 = __floats2half2_rn(w_lin_in[t * 64 + 2 * l],
                                           w_lin_in[t * 64 + 2 * l + 1]);
            __half2 z2 = __floats2half2_rn(0.f, 0.f);
            uint4 f4;
            f4.x = *(unsigned*)&s2; f4.y = *(unsigned*)&z2;
            f4.z = *(unsigned*)&z2; f4.w = *(unsigned*)&z2;
            g_feat[i] = f4;
        }
    }
}

// ---------------- single-block exclusive scan ----------------
__global__ void k_scan(int N) {
    __shared__ int sm[1024];
    int tid = threadIdx.x;
    int per = (N + 1023) >> 10;
    int st = tid * per;
    int s = 0;
    for (int i = 0; i < per; i++) { int idx = st + i; if (idx < N) s += g_hist[idx]; }
    sm[tid] = s;
    __syncthreads();
    for (int d = 1; d < 1024; d <<= 1) {
        int v = (tid >= d) ? sm[tid - d] : 0;
        __syncthreads();
        sm[tid] += v;
        __syncthreads();
    }
    int pre = tid ? sm[tid - 1] : 0;
    for (int i = 0; i < per; i++) {
        int idx = st + i;
        if (idx < N) { g_off[idx] = pre; g_cur[idx] = pre; pre += g_hist[idx]; }
    }
    if (tid == 0) g_off[N] = sm[1023];
}

// -------- scatter into dst-sorted order; also re-zero g_hist for next replay --------
__global__ void k_scatter(const int* __restrict__ edst, int E, int N) {
    int e = blockIdx.x * blockDim.x + threadIdx.x;
    if (e < N) g_hist[e] = 0;
    if (e >= E) return;
    uint4 rec = g_ev[e];
    if (rec.w == 0xFFFFFFFFu) return;   // filtered
    int d = edst[e];
    int p = atomicAdd(&g_cur[d], 1);
    g_rec[p] = rec;
}

#define H2(u) (*(__half2*)&(u))

// per-edge message math in half2; accumulates into 4 half2 accumulators
__device__ __forceinline__ void edge_msg(uint4 rc, uint4 qv, unsigned q5, uint4 ft,
                                         __half2& hS, __half2& hX,
                                         __half2& hY, __half2& hZ) {
    __half2 w1 = H2(qv.x), w2 = H2(qv.y), w3 = H2(qv.z), w4 = H2(qv.w), w5 = H2(q5);
    __half2 s01 = H2(ft.x), vx = H2(ft.y), vy = H2(ft.z), vz = H2(ft.w);
    __half2 yx2 = H2(rc.x), yy2 = H2(rc.y), yz2 = H2(rc.z);
    __half2 vd = __hfma2(vz, yz2, __hfma2(vy, yy2, __hmul2(vx, yx2)));
    hS = __hadd2(hS, __hfma2(w2, vd, __hmul2(w1, s01)));
    __half2 t3 = __hmul2(w3, s01);
    __half2 nvx = __hneg2(vx), nvy = __hneg2(vy), nvz = __hneg2(vz);
    __half2 cxh = __hfma2(nvz, yy2, __hmul2(vy, yz2));
    __half2 cyh = __hfma2(nvx, yz2, __hmul2(vz, yx2));
    __half2 czh = __hfma2(nvy, yx2, __hmul2(vx, yy2));
    hX = __hadd2(hX, __hfma2(w5, cxh, __hfma2(w4, vx, __hmul2(t3, yx2))));
    hY = __hadd2(hY, __hfma2(w5, cyh, __hfma2(w4, vy, __hmul2(t3, yy2))));
    hZ = __hadd2(hZ, __hfma2(w5, czh, __hfma2(w4, vz, __hmul2(t3, yz2))));
}

// ------- main per-layer aggregate: TWO warps per dst atom (even/odd edges),
//         software-pipelined chunks of 2 edges, half2 math, fp32 flush per chunk -------
__global__ void k_aggregate(int L, int N) {
    __shared__ float red[4][8][32];
    int tid = threadIdx.x;
    int lane = tid & 31;
    int warpInBlk = tid >> 5;
    int atomInBlk = warpInBlk >> 1;
    int half = warpInBlk & 1;
    int atom = blockIdx.x * 4 + atomInBlk;
    int valid = atom < N;
    int o0 = valid ? g_off[atom] : 0;
    int o1 = valid ? g_off[atom + 1] : 0;
    int c0 = lane << 1;
    float aS0 = 0, aS1 = 0, aX0 = 0, aX1 = 0, aY0 = 0, aY1 = 0, aZ0 = 0, aZ1 = 0;
    const uint4* tV = g_tV + (size_t)L * NTAB * 32;
    const unsigned* t5 = g_t5 + (size_t)L * NTAB * 32;
    const __half2 hz2 = __floats2half2_rn(0.f, 0.f);

    int p0 = o0 + half;
    int cnt = o1 - p0; cnt = cnt > 0 ? (cnt + 1) >> 1 : 0;  // edges this warp (stride 2)
    int nch = cnt >> 1;            // full 2-edge chunks
    int tailp = p0 + (nch << 2);   // first tail edge

    if (nch > 0) {
        // chunk 0: recs, then dependent loads
        uint4 rAn = g_rec[p0];
        uint4 rBn = g_rec[p0 + 2];
        int ibA = (int)(rAn.w & 0xFFFu) * 32 + lane;
        int ibB = (int)(rBn.w & 0xFFFu) * 32 + lane;
        uint4 qvA = tV[ibA]; unsigned q5A = t5[ibA];
        uint4 ftA = g_feat[(int)(rAn.w >> 12) * 32 + lane];
        uint4 qvB = tV[ibB]; unsigned q5B = t5[ibB];
        uint4 ftB = g_feat[(int)(rBn.w >> 12) * 32 + lane];
        uint4 rA = rAn, rB = rBn;
        if (nch > 1) { rAn = g_rec[p0 + 4]; rBn = g_rec[p0 + 6]; }
        int c = 0;
        for (;;) {
            // snapshot current chunk
            uint4 cqvA = qvA, cftA = ftA, cqvB = qvB, cftB = ftB;
            unsigned cq5A = q5A, cq5B = q5B;
            uint4 crA = rA, crB = rB;
            ++c;
            if (c < nch) {
                // issue next chunk's dependent loads; prefetch chunk after's recs
                int jbA = (int)(rAn.w & 0xFFFu) * 32 + lane;
                int jbB = (int)(rBn.w & 0xFFFu) * 32 + lane;
                qvA = tV[jbA]; q5A = t5[jbA];
                ftA = g_feat[(int)(rAn.w >> 12) * 32 + lane];
                qvB = tV[jbB]; q5B = t5[jbB];
                ftB = g_feat[(int)(rBn.w >> 12) * 32 + lane];
                rA = rAn; rB = rBn;
                if (c + 1 < nch) {
                    rAn = g_rec[p0 + (c + 1) * 4];
                    rBn = g_rec[p0 + (c + 1) * 4 + 2];
                }
            }
            // math on snapshot (overlaps the loads just issued)
            __half2 hS = hz2, hX = hz2, hY = hz2, hZ = hz2;
            edge_msg(crA, cqvA, cq5A, cftA, hS, hX, hY, hZ);
            edge_msg(crB, cqvB, cq5B, cftB, hS, hX, hY, hZ);
            float2 f;
            f = __half22float2(hS); aS0 += f.x; aS1 += f.y;
            f = __half22float2(hX); aX0 += f.x; aX1 += f.y;
            f = __half22float2(hY); aY0 += f.x; aY1 += f.y;
            f = __half22float2(hZ); aZ0 += f.x; aZ1 += f.y;
            if (c >= nch) break;
        }
    }
    // tail: at most 1 edge
    for (int p = tailp; p < o1; p += 2) {
        uint4 rc = g_rec[p];
        int ib = (int)(rc.w & 0xFFFu) * 32 + lane;
        uint4 qv = tV[ib];
        unsigned q5 = t5[ib];
        uint4 ft = g_feat[(int)(rc.w >> 12) * 32 + lane];
        __half2 hS = hz2, hX = hz2, hY = hz2, hZ = hz2;
        edge_msg(rc, qv, q5, ft, hS, hX, hY, hZ);
        float2 f;
        f = __half22float2(hS); aS0 += f.x; aS1 += f.y;
        f = __half22float2(hX); aX0 += f.x; aX1 += f.y;
        f = __half22float2(hY); aY0 += f.x; aY1 += f.y;
        f = __half22float2(hZ); aZ0 += f.x; aZ1 += f.y;
    }

    // cross-warp reduction (odd half -> smem, even half combines & writes)
    if (half) {
        red[atomInBlk][0][lane] = aS0; red[atomInBlk][1][lane] = aS1;
        red[atomInBlk][2][lane] = aX0; red[atomInBlk][3][lane] = aX1;
        red[atomInBlk][4][lane] = aY0; red[atomInBlk][5][lane] = aY1;
        red[atomInBlk][6][lane] = aZ0; red[atomInBlk][7][lane] = aZ1;
    }
    __syncthreads();
    if (!half && valid) {
        aS0 += red[atomInBlk][0][lane]; aS1 += red[atomInBlk][1][lane];
        aX0 += red[atomInBlk][2][lane]; aX1 += red[atomInBlk][3][lane];
        aY0 += red[atomInBlk][4][lane]; aY1 += red[atomInBlk][5][lane];
        aZ0 += red[atomInBlk][6][lane]; aZ1 += red[atomInBlk][7][lane];
        *(float2*)(g_as + atom * 64 + c0) = make_float2(aS0, aS1);
        float* ov = g_av + atom * 192 + c0;
        *(float2*)(ov) = make_float2(aX0, aX1);
        *(float2*)(ov + 64) = make_float2(aY0, aY1);
        *(float2*)(ov + 128) = make_float2(aZ0, aZ1);
    }
}

// ---- node self-interaction + resnet (+feat mirror); 4 atoms per warp ----
__global__ void k_node(int L, int N, const float* __restrict__ wss,
                       const float* __restrict__ wsv,
                       const float* __restrict__ wgt) {
    __shared__ float sWs[4096];
    __shared__ float sWv[4096];
    __shared__ float sWg[4096];
    const float* ps = wss + (size_t)L * 4096;
    const float* pv = wsv + (size_t)L * 4096;
    const float* pg = wgt + (size_t)L * 4096;
    for (int i = threadIdx.x; i < 4096; i += blockDim.x) {
        sWs[i] = ps[i]; sWv[i] = pv[i]; sWg[i] = pg[i];
    }
    __syncthreads();
    int lane = threadIdx.x & 31;
    int c0 = lane << 1;
    int baseAtom = blockIdx.x * 32 + (threadIdx.x >> 5) * 4;
    for (int a = 0; a < 4; a++) {
        int gw = baseAtom + a;
        if (gw >= N) break;
        float2 aa = *(const float2*)(g_as + gw * 64 + c0);
        const float* avp = g_av + gw * 192 + c0;
        float2 ax = *(const float2*)(avp);
        float2 ay = *(const float2*)(avp + 64);
        float2 az = *(const float2*)(avp + 128);
        float gs0 = 0, gs1 = 0, t0 = 0, t1 = 0;
        float vx0 = 0, vx1 = 0, vy0 = 0, vy1 = 0, vz0 = 0, vz1 = 0;
#pragma unroll
        for (int j = 0; j < 64; j++) {
            int sl = j >> 1;
            float aj = __shfl_sync(0xffffffffu, (j & 1) ? aa.y : aa.x, sl);
            float jx = __shfl_sync(0xffffffffu, (j & 1) ? ax.y : ax.x, sl);
            float jy = __shfl_sync(0xffffffffu, (j & 1) ? ay.y : ay.x, sl);
            float jz = __shfl_sync(0xffffffffu, (j & 1) ? az.y : az.x, sl);
            float2 wg2 = *(const float2*)(sWg + j * 64 + c0);
            float2 ws2 = *(const float2*)(sWs + j * 64 + c0);
            float2 wv2 = *(const float2*)(sWv + j * 64 + c0);
            gs0 += aj * wg2.x; gs1 += aj * wg2.y;
            t0 += aj * ws2.x;  t1 += aj * ws2.y;
            vx0 += jx * wv2.x; vx1 += jx * wv2.y;
            vy0 += jy * wv2.x; vy1 += jy * wv2.y;
            vz0 += jz * wv2.x; vz1 += jz * wv2.y;
        }
        float g0 = 1.f / (1.f + expf(-gs0));
        float g1 = 1.f / (1.f + expf(-gs1));
        float si0 = t0 / (1.f + expf(-t0));
        float si1 = t1 / (1.f + expf(-t1));
        float* sp = g_s + gw * 64 + c0;
        float2 sv = *(float2*)sp;
        sv.x += si0; sv.y += si1;
        *(float2*)sp = sv;
        float* vp = g_v + gw * 192 + c0;
        float2 v1, v2, v3;
        v1 = *(float2*)(vp);       v1.x += vx0 * g0; v1.y += vx1 * g1; *(float2*)(vp) = v1;
        v2 = *(float2*)(vp + 64);  v2.x += vy0 * g0; v2.y += vy1 * g1; *(float2*)(vp + 64) = v2;
        v3 = *(float2*)(vp + 128); v3.x += vz0 * g0; v3.y += vz1 * g1; *(float2*)(vp + 128) = v3;
        __half2 hs = __floats2half2_rn(sv.x, sv.y);
        __half2 h1 = __floats2half2_rn(v1.x, v1.y);
        __half2 h2 = __floats2half2_rn(v2.x, v2.y);
        __half2 h3 = __floats2half2_rn(v3.x, v3.y);
        uint4 f4;
        f4.x = *(unsigned*)&hs; f4.y = *(unsigned*)&h1;
        f4.z = *(unsigned*)&h2; f4.w = *(unsigned*)&h3;
        g_feat[gw * 32 + lane] = f4;
    }
}

// ---------------- final energy head ----------------
__global__ void k_energy(int N, const float* __restrict__ wl1,
                         const float* __restrict__ wl2,
                         float* __restrict__ out) {
    __shared__ float sW[1024];
    __shared__ float sw2[16];
    for (int i = threadIdx.x; i < 1024; i += blockDim.x) sW[i] = wl1[i];
    if (threadIdx.x < 16) sw2[threadIdx.x] = wl2[threadIdx.x];
    __syncthreads();
    int gw = blockIdx.x * 8 + (threadIdx.x >> 5);
    if (gw >= N) return;
    int lane = threadIdx.x & 31;
    int c0 = lane << 1;
    float2 s = *(const float2*)(g_s + gw * 64 + c0);
    float p[16];
#pragma unroll
    for (int k = 0; k < 16; k++)
        p[k] = s.x * sW[c0 * 16 + k] + s.y * sW[(c0 + 1) * 16 + k];
#pragma unroll
    for (int d = 16; d >= 1; d >>= 1) {
#pragma unroll
        for (int k = 0; k < 16; k++) p[k] += __shfl_down_sync(0xffffffffu, p[k], d);
    }
    if (lane == 0) {
        float e = 0.f;
#pragma unroll
        for (int k = 0; k < 16; k++) e += p[k] * sw2[k];
        out[gw] = e;
    }
}

// ---------------- launch ----------------
extern "C" void kernel_launch(void* const* d_in, const int* in_sizes, int n_in,
                              void* d_out, int out_size) {
    const int*   atom_type = (const int*)d_in[0];
    const float* atom_pos  = (const float*)d_in[1];
    const int*   edge_src  = (const int*)d_in[2];
    const int*   edge_dst  = (const int*)d_in[3];
    const float* shift     = (const float*)d_in[4];
    const float* cell      = (const float*)d_in[5];
    const int*   image_idx = (const int*)d_in[6];
    const float* w_lin_in  = (const float*)d_in[7];
    const float* mw1       = (const float*)d_in[8];
    const float* mb1       = (const float*)d_in[9];
    const float* mw2       = (const float*)d_in[10];
    const float* wss       = (const float*)d_in[11];
    const float* wsv       = (const float*)d_in[12];
    const float* wgt       = (const float*)d_in[13];
    const float* wl1       = (const float*)d_in[14];
    const float* wl2       = (const float*)d_in[15];
    int N = in_sizes[0];
    int E = in_sizes[2];
    float* out = (float*)d_out;

    int nEdgeBlk = (E + 255) / 256;
    int nTabBlk  = NLAYERS * (NTAB / ENT);
    int nInitBlk = (N * 192 + 255) / 256;

    k_mega<<<nEdgeBlk + nTabBlk + nInitBlk, 256>>>(
        atom_pos, edge_src, edge_dst, shift, cell, image_idx,
        atom_type, w_lin_in, mw1, mb1, mw2, E, N, nEdgeBlk, nTabBlk);
    k_scan<<<1, 1024>>>(N);
    k_scatter<<<(E + 255) / 256, 256>>>(edge_dst, E, N);
    for (int L = 0; L < NLAYERS; ++L) {
        k_aggregate<<<(N + 3) / 4, 256>>>(L, N);
        k_node<<<(N + 31) / 32, 256>>>(L, N, wss, wsv, wgt);
    }
    k_energy<<<(N + 7) / 8, 256>>>(N, wl1, wl2, out);
}

// round 13
// speedup vs baseline: 1.0808x; 1.0483x over previous
#include <cuda_runtime.h>
#include <cuda_fp16.h>
#include <math.h>

#define MAXN 16384
#define MAXE 524288
#define NTAB 4096
#define RMAXF 5.0f
#define NLAYERS 3
#define ENT 16
#define JT 16

// ---------------- static scratch (no allocation allowed) ----------------
__device__ uint4     g_ev[MAXE];        // unsorted: {yx h2, yy h2, yz h2, (src<<12)|i0}
__device__ uint4     g_rec[MAXE];       // dst-sorted records (same format)
__device__ int       g_hist[MAXN];      // zeroed by k_scatter for next replay
__device__ int       g_cur[MAXN];
__device__ int       g_off[MAXN + 1];
// nearest-entry half tables per lane: vals paths1-4 (16B), val path5 (4B)
__device__ uint4     g_tV[NLAYERS * NTAB * 32];
__device__ unsigned  g_t5[NLAYERS * NTAB * 32];
__device__ float     g_s[MAXN * 64];
__device__ float     g_v[MAXN * 192];   // layout [n][3][64]
__device__ float     g_as[MAXN * 64];
__device__ float     g_av[MAXN * 192];
__device__ uint4     g_feat[MAXN * 32]; // per lane: {s h2, vx h2, vy h2, vz h2}

// ================= mega kernel: edge_pre | table build | init =================
__global__ void k_mega(const float* __restrict__ pos,
                       const int* __restrict__ esrc,
                       const int* __restrict__ edst,
                       const float* __restrict__ shift,
                       const float* __restrict__ cell,
                       const int* __restrict__ img,
                       const int* __restrict__ atom_type,
                       const float* __restrict__ w_lin_in,
                       const float* __restrict__ mw1,
                       const float* __restrict__ mb1,
                       const float* __restrict__ mw2,
                       int E, int N, int nEdgeBlk, int nTabBlk) {
    __shared__ float sh_h[ENT * 64];   // 4KB  (table branch)
    __shared__ float sh_w[JT * 320];   // 20KB (table branch)
    int b = blockIdx.x;
    int tid = threadIdx.x;

    if (b < nEdgeBlk) {
        // ---- edge preprocess ----
        int e = b * 256 + tid;
        if (e >= E) return;
        int s = esrc[e], d = edst[e];
        float vx = pos[d * 3 + 0] - pos[s * 3 + 0];
        float vy = pos[d * 3 + 1] - pos[s * 3 + 1];
        float vz = pos[d * 3 + 2] - pos[s * 3 + 2];
        float s0 = shift[e * 3 + 0], s1 = shift[e * 3 + 1], s2 = shift[e * 3 + 2];
        const float* Cm = cell + img[s] * 9;
        vx += s0 * Cm[0] + s1 * Cm[3] + s2 * Cm[6];
        vy += s0 * Cm[1] + s1 * Cm[4] + s2 * Cm[7];
        vz += s0 * Cm[2] + s1 * Cm[5] + s2 * Cm[8];
        float r = sqrtf(vx * vx + vy * vy + vz * vz);
        uint4 rec;
        if (r < RMAXF) {
            float inv = 1.7320508075688772f / fmaxf(r, 1e-9f);  // sqrt3 * unit
            __half2 hx = __half2half2(__float2half_rn(vx * inv));
            __half2 hy = __half2half2(__float2half_rn(vy * inv));
            __half2 hz = __half2half2(__float2half_rn(vz * inv));
            int i0 = __float2int_rn(r * ((float)(NTAB - 1) / RMAXF));
            if (i0 > NTAB - 1) i0 = NTAB - 1;
            rec.x = *(unsigned*)&hx; rec.y = *(unsigned*)&hy;
            rec.z = *(unsigned*)&hz;
            rec.w = ((unsigned)s << 12) | (unsigned)i0;
            atomicAdd(&g_hist[d], 1);
        } else {
            rec.x = rec.y = rec.z = 0;
            rec.w = 0xFFFFFFFFu;   // filtered marker
        }
        g_ev[e] = rec;
    } else if (b < nEdgeBlk + nTabBlk) {
        // ---- fused table build: h in-block, GEMM, pack ----
        int tb = b - nEdgeBlk;
        int L = tb / (NTAB / ENT);
        int e_blk = (tb % (NTAB / ENT)) * ENT;
        for (int i = tid; i < ENT * 64; i += 256) {
            int el = i >> 6, t = i & 63;
            int entry = e_blk + el;
            float r = (float)entry * (RMAXF / (float)(NTAB - 1));
            float rs = fmaxf(r, 1e-9f);
            float x = r / RMAXF;
            float x2 = x * x;
            float x6 = x2 * x2 * x2;
            float fc = 1.f - 28.f * x6 + 48.f * x6 * x - 21.f * x6 * x2;
            if (x >= 1.f) fc = 0.f;
            float cscale = sqrtf(2.f / RMAXF) * fc / rs;
            float arg = 3.14159265358979323846f * rs / RMAXF;
            float h = mb1[L * 64 + t];
#pragma unroll
            for (int j = 0; j < 8; j++)
                h += cscale * sinf((float)(j + 1) * arg) * mw1[(L * 8 + j) * 64 + t];
            sh_h[i] = h / (1.f + expf(-h));  // silu
        }

        int c = tid & 63;
        int eg = tid >> 6;
        float acc[4][5];
#pragma unroll
        for (int q = 0; q < 4; q++)
#pragma unroll
            for (int k = 0; k < 5; k++) acc[q][k] = 0.f;

        for (int j0 = 0; j0 < 64; j0 += JT) {
            __syncthreads();
            const float* wsrc = mw2 + ((size_t)L * 64 + j0) * 320;
            for (int i = tid; i < JT * 320; i += 256) sh_w[i] = wsrc[i];
            __syncthreads();
#pragma unroll
            for (int j = 0; j < JT; j++) {
                float w0 = sh_w[j * 320 + 0 * 64 + c];
                float w1 = sh_w[j * 320 + 1 * 64 + c];
                float w2 = sh_w[j * 320 + 2 * 64 + c];
                float w3 = sh_w[j * 320 + 3 * 64 + c];
                float w4 = sh_w[j * 320 + 4 * 64 + c];
#pragma unroll
                for (int q = 0; q < 4; q++) {
                    float hj = sh_h[(eg * 4 + q) * 64 + j0 + j];
                    acc[q][0] += hj * w0;
                    acc[q][1] += hj * w1;
                    acc[q][2] += hj * w2;
                    acc[q][3] += hj * w3;
                    acc[q][4] += hj * w4;
                }
            }
        }
        const float ISD = 0.17677669529663687f;          // 1/sqrt(32)
        const float SC[5] = {ISD, ISD * 0.57735026918962576f, ISD, ISD,
                             ISD * 0.70710678118654752f};
        __syncthreads();
#pragma unroll
        for (int q = 0; q < 4; q++)
#pragma unroll
            for (int k = 0; k < 5; k++)
                sh_w[(eg * 4 + q) * 320 + k * 64 + c] = acc[q][k] * SC[k];
        __syncthreads();
        for (int u = tid; u < ENT * 32; u += 256) {
            int el = u >> 5, lane = u & 31, cc = lane * 2;
            const float* row = sh_w + el * 320;
            __half2 p1 = __floats2half2_rn(row[0 * 64 + cc], row[0 * 64 + cc + 1]);
            __half2 p2 = __floats2half2_rn(row[1 * 64 + cc], row[1 * 64 + cc + 1]);
            __half2 p3 = __floats2half2_rn(row[2 * 64 + cc], row[2 * 64 + cc + 1]);
            __half2 p4 = __floats2half2_rn(row[3 * 64 + cc], row[3 * 64 + cc + 1]);
            __half2 p5 = __floats2half2_rn(row[4 * 64 + cc], row[4 * 64 + cc + 1]);
            size_t base = ((size_t)L * NTAB + e_blk + el) * 32 + lane;
            g_tV[base] = make_uint4(*(unsigned*)&p1, *(unsigned*)&p2,
                                    *(unsigned*)&p3, *(unsigned*)&p4);
            g_t5[base] = *(unsigned*)&p5;
        }
    } else {
        // ---- node feature init ----
        int i = (b - nEdgeBlk - nTabBlk) * 256 + tid;
        if (i < N * 192) g_v[i] = 0.f;
        if (i < N * 64) {
            int n = i >> 6, cc = i & 63;
            g_s[i] = w_lin_in[atom_type[n] * 64 + cc];
        }
        if (i < N * 32) {
            int n = i >> 5, l = i & 31;
            int t = atom_type[n];
            __half2 s2 = __floats2half2_rn(w_lin_in[t * 64 + 2 * l],
                                           w_lin_in[t * 64 + 2 * l + 1]);
            __half2 z2 = __floats2half2_rn(0.f, 0.f);
            uint4 f4;
            f4.x = *(unsigned*)&s2; f4.y = *(unsigned*)&z2;
            f4.z = *(unsigned*)&z2; f4.w = *(unsigned*)&z2;
            g_feat[i] = f4;
        }
    }
}

// ---------------- single-block exclusive scan ----------------
__global__ void k_scan(int N) {
    __shared__ int sm[1024];
    int tid = threadIdx.x;
    int per = (N + 1023) >> 10;
    int st = tid * per;
    int s = 0;
    for (int i = 0; i < per; i++) { int idx = st + i; if (idx < N) s += g_hist[idx]; }
    sm[tid] = s;
    __syncthreads();
    for (int d = 1; d < 1024; d <<= 1) {
        int v = (tid >= d) ? sm[tid - d] : 0;
        __syncthreads();
        sm[tid] += v;
        __syncthreads();
    }
    int pre = tid ? sm[tid - 1] : 0;
    for (int i = 0; i < per; i++) {
        int idx = st + i;
        if (idx < N) { g_off[idx] = pre; g_cur[idx] = pre; pre += g_hist[idx]; }
    }
    if (tid == 0) g_off[N] = sm[1023];
}

// -------- scatter into dst-sorted order; also re-zero g_hist for next replay --------
__global__ void k_scatter(const int* __restrict__ edst, int E, int N) {
    int e = blockIdx.x * blockDim.x + threadIdx.x;
    if (e < N) g_hist[e] = 0;
    if (e >= E) return;
    uint4 rec = g_ev[e];
    if (rec.w == 0xFFFFFFFFu) return;   // filtered
    int d = edst[e];
    int p = atomicAdd(&g_cur[d], 1);
    g_rec[p] = rec;
}

#define H2(u) (*(__half2*)&(u))

// per-edge message math in half2; accumulation folded into the fma chains
__device__ __forceinline__ void edge_acc(uint4 rc, uint4 qv, unsigned q5, uint4 ft,
                                         __half2& hS, __half2& hX,
                                         __half2& hY, __half2& hZ) {
    __half2 w1 = H2(qv.x), w2 = H2(qv.y), w3 = H2(qv.z), w4 = H2(qv.w), w5 = H2(q5);
    __half2 s01 = H2(ft.x), vx = H2(ft.y), vy = H2(ft.z), vz = H2(ft.w);
    __half2 yx2 = H2(rc.x), yy2 = H2(rc.y), yz2 = H2(rc.z);
    __half2 vd = __hfma2(vz, yz2, __hfma2(vy, yy2, __hmul2(vx, yx2)));
    hS = __hfma2(w1, s01, __hfma2(w2, vd, hS));
    __half2 t3 = __hmul2(w3, s01);
    __half2 cxh = __hfma2(__hneg2(vz), yy2, __hmul2(vy, yz2));
    __half2 cyh = __hfma2(__hneg2(vx), yz2, __hmul2(vz, yx2));
    __half2 czh = __hfma2(__hneg2(vy), yx2, __hmul2(vx, yy2));
    hX = __hfma2(w5, cxh, __hfma2(w4, vx, __hfma2(t3, yx2, hX)));
    hY = __hfma2(w5, cyh, __hfma2(w4, vy, __hfma2(t3, yy2, hY)));
    hZ = __hfma2(w5, czh, __hfma2(w4, vz, __hfma2(t3, yz2, hZ)));
}

// ------- main per-layer aggregate: TWO warps per dst atom (even/odd edges),
//         copy-free double-buffered pipeline, half2 math, fp32 flush per pair -------
__global__ void k_aggregate(int L, int N) {
    __shared__ float red[4][8][32];
    int tid = threadIdx.x;
    int lane = tid & 31;
    int warpInBlk = tid >> 5;
    int atomInBlk = warpInBlk >> 1;
    int half = warpInBlk & 1;
    int atom = blockIdx.x * 4 + atomInBlk;
    int valid = atom < N;
    int o0 = valid ? g_off[atom] : 0;
    int o1 = valid ? g_off[atom + 1] : 0;
    int c0 = lane << 1;
    float aS0 = 0, aS1 = 0, aX0 = 0, aX1 = 0, aY0 = 0, aY1 = 0, aZ0 = 0, aZ1 = 0;
    const uint4* tV = g_tV + (size_t)L * NTAB * 32;
    const unsigned* t5 = g_t5 + (size_t)L * NTAB * 32;
    const __half2 hz2 = __floats2half2_rn(0.f, 0.f);

    int p = o0 + half;                     // edges p, p+2, ...
    int m = o1 - p; m = m > 0 ? (m + 1) >> 1 : 0;   // # edges this warp

    if (m > 0) {
        // prologue — slot A (edge 0), slot B (edge 1), rec queue for edges 2,3
        uint4 recA = g_rec[p];
        int ibA = (int)(recA.w & 0xFFFu) * 32 + lane;
        uint4 qvA = tV[ibA]; unsigned q5A = t5[ibA];
        uint4 ftA = g_feat[(int)(recA.w >> 12) * 32 + lane];

        uint4 recB, qvB, ftB; unsigned q5B = 0;
        if (m > 1) {
            recB = g_rec[p + 2];
            int ibB = (int)(recB.w & 0xFFFu) * 32 + lane;
            qvB = tV[ibB]; q5B = t5[ibB];
            ftB = g_feat[(int)(recB.w >> 12) * 32 + lane];
        }
        uint4 recQ0 = g_rec[p + 4];   // edge 2 (garbage-safe: array has slack)
        uint4 recQ1 = g_rec[p + 6];   // edge 3

        int k = 0;
        // main loop: processes pair (k, k+1); requires edges k+2,k+3 valid for reload
        for (; k + 3 < m; k += 2) {
            __half2 hS = hz2, hX = hz2, hY = hz2, hZ = hz2;
            // edge k (slot A)
            edge_acc(recA, qvA, q5A, ftA, hS, hX, hY, hZ);
            recA = recQ0;                              // rec for edge k+2 (resident)
            {
                int ib = (int)(recA.w & 0xFFFu) * 32 + lane;
                qvA = tV[ib]; q5A = t5[ib];
                ftA = g_feat[(int)(recA.w >> 12) * 32 + lane];
            }
            recQ0 = g_rec[p + 2 * (k + 4)];            // rec for edge k+4
            // edge k+1 (slot B)
            edge_acc(recB, qvB, q5B, ftB, hS, hX, hY, hZ);
            recB = recQ1;                              // rec for edge k+3 (resident)
            {
                int ib = (int)(recB.w & 0xFFFu) * 32 + lane;
                qvB = tV[ib]; q5B = t5[ib];
                ftB = g_feat[(int)(recB.w >> 12) * 32 + lane];
            }
            recQ1 = g_rec[p + 2 * (k + 5)];            // rec for edge k+5
            // flush pair to fp32
            float2 f;
            f = __half22float2(hS); aS0 += f.x; aS1 += f.y;
            f = __half22float2(hX); aX0 += f.x; aX1 += f.y;
            f = __half22float2(hY); aY0 += f.x; aY1 += f.y;
            f = __half22float2(hZ); aZ0 += f.x; aZ1 += f.y;
        }
        // drain: at most edges k, k+1, k+2
        {
            __half2 hS = hz2, hX = hz2, hY = hz2, hZ = hz2;
            if (k < m)     edge_acc(recA, qvA, q5A, ftA, hS, hX, hY, hZ);
            if (k + 1 < m) edge_acc(recB, qvB, q5B, ftB, hS, hX, hY, hZ);
            if (k + 2 < m) {
                int ib = (int)(recQ0.w & 0xFFFu) * 32 + lane;
                uint4 qv = tV[ib];
                unsigned q5v = t5[ib];
                uint4 ft = g_feat[(int)(recQ0.w >> 12) * 32 + lane];
                edge_acc(recQ0, qv, q5v, ft, hS, hX, hY, hZ);
            }
            float2 f;
            f = __half22float2(hS); aS0 += f.x; aS1 += f.y;
            f = __half22float2(hX); aX0 += f.x; aX1 += f.y;
            f = __half22float2(hY); aY0 += f.x; aY1 += f.y;
            f = __half22float2(hZ); aZ0 += f.x; aZ1 += f.y;
        }
    }

    // cross-warp reduction (odd half -> smem, even half combines & writes)
    if (half) {
        red[atomInBlk][0][lane] = aS0; red[atomInBlk][1][lane] = aS1;
        red[atomInBlk][2][lane] = aX0; red[atomInBlk][3][lane] = aX1;
        red[atomInBlk][4][lane] = aY0; red[atomInBlk][5][lane] = aY1;
        red[atomInBlk][6][lane] = aZ0; red[atomInBlk][7][lane] = aZ1;
    }
    __syncthreads();
    if (!half && valid) {
        aS0 += red[atomInBlk][0][lane]; aS1 += red[atomInBlk][1][lane];
        aX0 += red[atomInBlk][2][lane]; aX1 += red[atomInBlk][3][lane];
        aY0 += red[atomInBlk][4][lane]; aY1 += red[atomInBlk][5][lane];
        aZ0 += red[atomInBlk][6][lane]; aZ1 += red[atomInBlk][7][lane];
        *(float2*)(g_as + atom * 64 + c0) = make_float2(aS0, aS1);
        float* ov = g_av + atom * 192 + c0;
        *(float2*)(ov) = make_float2(aX0, aX1);
        *(float2*)(ov + 64) = make_float2(aY0, aY1);
        *(float2*)(ov + 128) = make_float2(aZ0, aZ1);
    }
}

// ---- node self-interaction + resnet (+feat mirror); 4 atoms per warp ----
__global__ void k_node(int L, int N, const float* __restrict__ wss,
                       const float* __restrict__ wsv,
                       const float* __restrict__ wgt) {
    __shared__ float sWs[4096];
    __shared__ float sWv[4096];
    __shared__ float sWg[4096];
    const float* ps = wss + (size_t)L * 4096;
    const float* pv = wsv + (size_t)L * 4096;
    const float* pg = wgt + (size_t)L * 4096;
    for (int i = threadIdx.x; i < 4096; i += blockDim.x) {
        sWs[i] = ps[i]; sWv[i] = pv[i]; sWg[i] = pg[i];
    }
    __syncthreads();
    int lane = threadIdx.x & 31;
    int c0 = lane << 1;
    int baseAtom = blockIdx.x * 32 + (threadIdx.x >> 5) * 4;
    for (int a = 0; a < 4; a++) {
        int gw = baseAtom + a;
        if (gw >= N) break;
        float2 aa = *(const float2*)(g_as + gw * 64 + c0);
        const float* avp = g_av + gw * 192 + c0;
        float2 ax = *(const float2*)(avp);
        float2 ay = *(const float2*)(avp + 64);
        float2 az = *(const float2*)(avp + 128);
        float gs0 = 0, gs1 = 0, t0 = 0, t1 = 0;
        float vx0 = 0, vx1 = 0, vy0 = 0, vy1 = 0, vz0 = 0, vz1 = 0;
#pragma unroll
        for (int j = 0; j < 64; j++) {
            int sl = j >> 1;
            float aj = __shfl_sync(0xffffffffu, (j & 1) ? aa.y : aa.x, sl);
            float jx = __shfl_sync(0xffffffffu, (j & 1) ? ax.y : ax.x, sl);
            float jy = __shfl_sync(0xffffffffu, (j & 1) ? ay.y : ay.x, sl);
            float jz = __shfl_sync(0xffffffffu, (j & 1) ? az.y : az.x, sl);
            float2 wg2 = *(const float2*)(sWg + j * 64 + c0);
            float2 ws2 = *(const float2*)(sWs + j * 64 + c0);
            float2 wv2 = *(const float2*)(sWv + j * 64 + c0);
            gs0 += aj * wg2.x; gs1 += aj * wg2.y;
            t0 += aj * ws2.x;  t1 += aj * ws2.y;
            vx0 += jx * wv2.x; vx1 += jx * wv2.y;
            vy0 += jy * wv2.x; vy1 += jy * wv2.y;
            vz0 += jz * wv2.x; vz1 += jz * wv2.y;
        }
        float g0 = 1.f / (1.f + expf(-gs0));
        float g1 = 1.f / (1.f + expf(-gs1));
        float si0 = t0 / (1.f + expf(-t0));
        float si1 = t1 / (1.f + expf(-t1));
        float* sp = g_s + gw * 64 + c0;
        float2 sv = *(float2*)sp;
        sv.x += si0; sv.y += si1;
        *(float2*)sp = sv;
        float* vp = g_v + gw * 192 + c0;
        float2 v1, v2, v3;
        v1 = *(float2*)(vp);       v1.x += vx0 * g0; v1.y += vx1 * g1; *(float2*)(vp) = v1;
        v2 = *(float2*)(vp + 64);  v2.x += vy0 * g0; v2.y += vy1 * g1; *(float2*)(vp + 64) = v2;
        v3 = *(float2*)(vp + 128); v3.x += vz0 * g0; v3.y += vz1 * g1; *(float2*)(vp + 128) = v3;
        __half2 hs = __floats2half2_rn(sv.x, sv.y);
        __half2 h1 = __floats2half2_rn(v1.x, v1.y);
        __half2 h2 = __floats2half2_rn(v2.x, v2.y);
        __half2 h3 = __floats2half2_rn(v3.x, v3.y);
        uint4 f4;
        f4.x = *(unsigned*)&hs; f4.y = *(unsigned*)&h1;
        f4.z = *(unsigned*)&h2; f4.w = *(unsigned*)&h3;
        g_feat[gw * 32 + lane] = f4;
    }
}

// ---------------- final energy head ----------------
__global__ void k_energy(int N, const float* __restrict__ wl1,
                         const float* __restrict__ wl2,
                         float* __restrict__ out) {
    __shared__ float sW[1024];
    __shared__ float sw2[16];
    for (int i = threadIdx.x; i < 1024; i += blockDim.x) sW[i] = wl1[i];
    if (threadIdx.x < 16) sw2[threadIdx.x] = wl2[threadIdx.x];
    __syncthreads();
    int gw = blockIdx.x * 8 + (threadIdx.x >> 5);
    if (gw >= N) return;
    int lane = threadIdx.x & 31;
    int c0 = lane << 1;
    float2 s = *(const float2*)(g_s + gw * 64 + c0);
    float p[16];
#pragma unroll
    for (int k = 0; k < 16; k++)
        p[k] = s.x * sW[c0 * 16 + k] + s.y * sW[(c0 + 1) * 16 + k];
#pragma unroll
    for (int d = 16; d >= 1; d >>= 1) {
#pragma unroll
        for (int k = 0; k < 16; k++) p[k] += __shfl_down_sync(0xffffffffu, p[k], d);
    }
    if (lane == 0) {
        float e = 0.f;
#pragma unroll
        for (int k = 0; k < 16; k++) e += p[k] * sw2[k];
        out[gw] = e;
    }
}

// ---------------- launch ----------------
extern "C" void kernel_launch(void* const* d_in, const int* in_sizes, int n_in,
                              void* d_out, int out_size) {
    const int*   atom_type = (const int*)d_in[0];
    const float* atom_pos  = (const float*)d_in[1];
    const int*   edge_src  = (const int*)d_in[2];
    const int*   edge_dst  = (const int*)d_in[3];
    const float* shift     = (const float*)d_in[4];
    const float* cell      = (const float*)d_in[5];
    const int*   image_idx = (const int*)d_in[6];
    const float* w_lin_in  = (const float*)d_in[7];
    const float* mw1       = (const float*)d_in[8];
    const float* mb1       = (const float*)d_in[9];
    const float* mw2       = (const float*)d_in[10];
    const float* wss       = (const float*)d_in[11];
    const float* wsv       = (const float*)d_in[12];
    const float* wgt       = (const float*)d_in[13];
    const float* wl1       = (const float*)d_in[14];
    const float* wl2       = (const float*)d_in[15];
    int N = in_sizes[0];
    int E = in_sizes[2];
    float* out = (float*)d_out;

    int nEdgeBlk = (E + 255) / 256;
    int nTabBlk  = NLAYERS * (NTAB / ENT);
    int nInitBlk = (N * 192 + 255) / 256;

    k_mega<<<nEdgeBlk + nTabBlk + nInitBlk, 256>>>(
        atom_pos, edge_src, edge_dst, shift, cell, image_idx,
        atom_type, w_lin_in, mw1, mb1, mw2, E, N, nEdgeBlk, nTabBlk);
    k_scan<<<1, 1024>>>(N);
    k_scatter<<<(E + 255) / 256, 256>>>(edge_dst, E, N);
    for (int L = 0; L < NLAYERS; ++L) {
        k_aggregate<<<(N + 3) / 4, 256>>>(L, N);
        k_node<<<(N + 31) / 32, 256>>>(L, N, wss, wsv, wgt);
    }
    k_energy<<<(N + 7) / 8, 256>>>(N, wl1, wl2, out);
}

// round 14
// speedup vs baseline: 1.1179x; 1.0343x over previous
#include <cuda_runtime.h>
#include <cuda_fp16.h>
#include <math.h>

#define MAXN 16384
#define MAXE 524288
#define NTAB 4096
#define RMAXF 5.0f
#define NLAYERS 3
#define ENT 16
#define JT 16

// ---------------- static scratch (no allocation allowed) ----------------
__device__ uint4     g_ev[MAXE];        // unsorted: {yx h2, yy h2, yz h2, (src<<12)|i0}
__device__ uint4     g_rec[MAXE];       // dst-sorted records (same format)
__device__ int       g_hist[MAXN];      // zeroed by k_scatter for next replay
__device__ int       g_cur[MAXN];
__device__ int       g_off[MAXN + 1];
// nearest-entry half tables per lane: vals paths1-4 (16B), val path5 (4B)
__device__ uint4     g_tV[NLAYERS * NTAB * 32];
__device__ unsigned  g_t5[NLAYERS * NTAB * 32];
__device__ float     g_s[MAXN * 64];
__device__ float     g_v[MAXN * 192];   // layout [n][3][64]
__device__ float     g_as[MAXN * 64];
__device__ float     g_av[MAXN * 192];
__device__ uint4     g_feat[MAXN * 32]; // per lane: {s h2, vx h2, vy h2, vz h2}

// ================= mega kernel: edge_pre | table build | init =================
__global__ void k_mega(const float* __restrict__ pos,
                       const int* __restrict__ esrc,
                       const int* __restrict__ edst,
                       const float* __restrict__ shift,
                       const float* __restrict__ cell,
                       const int* __restrict__ img,
                       const int* __restrict__ atom_type,
                       const float* __restrict__ w_lin_in,
                       const float* __restrict__ mw1,
                       const float* __restrict__ mb1,
                       const float* __restrict__ mw2,
                       int E, int N, int nEdgeBlk, int nTabBlk) {
    __shared__ float sh_h[ENT * 64];   // 4KB  (table branch)
    __shared__ float sh_w[JT * 320];   // 20KB (table branch)
    int b = blockIdx.x;
    int tid = threadIdx.x;

    if (b < nEdgeBlk) {
        // ---- edge preprocess ----
        int e = b * 256 + tid;
        if (e >= E) return;
        int s = esrc[e], d = edst[e];
        float vx = pos[d * 3 + 0] - pos[s * 3 + 0];
        float vy = pos[d * 3 + 1] - pos[s * 3 + 1];
        float vz = pos[d * 3 + 2] - pos[s * 3 + 2];
        float s0 = shift[e * 3 + 0], s1 = shift[e * 3 + 1], s2 = shift[e * 3 + 2];
        const float* Cm = cell + img[s] * 9;
        vx += s0 * Cm[0] + s1 * Cm[3] + s2 * Cm[6];
        vy += s0 * Cm[1] + s1 * Cm[4] + s2 * Cm[7];
        vz += s0 * Cm[2] + s1 * Cm[5] + s2 * Cm[8];
        float r = sqrtf(vx * vx + vy * vy + vz * vz);
        uint4 rec;
        if (r < RMAXF) {
            float inv = 1.7320508075688772f / fmaxf(r, 1e-9f);  // sqrt3 * unit
            __half2 hx = __half2half2(__float2half_rn(vx * inv));
            __half2 hy = __half2half2(__float2half_rn(vy * inv));
            __half2 hz = __half2half2(__float2half_rn(vz * inv));
            int i0 = __float2int_rn(r * ((float)(NTAB - 1) / RMAXF));
            if (i0 > NTAB - 1) i0 = NTAB - 1;
            rec.x = *(unsigned*)&hx; rec.y = *(unsigned*)&hy;
            rec.z = *(unsigned*)&hz;
            rec.w = ((unsigned)s << 12) | (unsigned)i0;
            atomicAdd(&g_hist[d], 1);
        } else {
            rec.x = rec.y = rec.z = 0;
            rec.w = 0xFFFFFFFFu;   // filtered marker
        }
        g_ev[e] = rec;
    } else if (b < nEdgeBlk + nTabBlk) {
        // ---- fused table build: h in-block, GEMM, pack ----
        int tb = b - nEdgeBlk;
        int L = tb / (NTAB / ENT);
        int e_blk = (tb % (NTAB / ENT)) * ENT;
        for (int i = tid; i < ENT * 64; i += 256) {
            int el = i >> 6, t = i & 63;
            int entry = e_blk + el;
            float r = (float)entry * (RMAXF / (float)(NTAB - 1));
            float rs = fmaxf(r, 1e-9f);
            float x = r / RMAXF;
            float x2 = x * x;
            float x6 = x2 * x2 * x2;
            float fc = 1.f - 28.f * x6 + 48.f * x6 * x - 21.f * x6 * x2;
            if (x >= 1.f) fc = 0.f;
            float cscale = sqrtf(2.f / RMAXF) * fc / rs;
            float arg = 3.14159265358979323846f * rs / RMAXF;
            float h = mb1[L * 64 + t];
#pragma unroll
            for (int j = 0; j < 8; j++)
                h += cscale * sinf((float)(j + 1) * arg) * mw1[(L * 8 + j) * 64 + t];
            sh_h[i] = h / (1.f + expf(-h));  // silu
        }

        int c = tid & 63;
        int eg = tid >> 6;
        float acc[4][5];
#pragma unroll
        for (int q = 0; q < 4; q++)
#pragma unroll
            for (int k = 0; k < 5; k++) acc[q][k] = 0.f;

        for (int j0 = 0; j0 < 64; j0 += JT) {
            __syncthreads();
            const float* wsrc = mw2 + ((size_t)L * 64 + j0) * 320;
            for (int i = tid; i < JT * 320; i += 256) sh_w[i] = wsrc[i];
            __syncthreads();
#pragma unroll
            for (int j = 0; j < JT; j++) {
                float w0 = sh_w[j * 320 + 0 * 64 + c];
                float w1 = sh_w[j * 320 + 1 * 64 + c];
                float w2 = sh_w[j * 320 + 2 * 64 + c];
                float w3 = sh_w[j * 320 + 3 * 64 + c];
                float w4 = sh_w[j * 320 + 4 * 64 + c];
#pragma unroll
                for (int q = 0; q < 4; q++) {
                    float hj = sh_h[(eg * 4 + q) * 64 + j0 + j];
                    acc[q][0] += hj * w0;
                    acc[q][1] += hj * w1;
                    acc[q][2] += hj * w2;
                    acc[q][3] += hj * w3;
                    acc[q][4] += hj * w4;
                }
            }
        }
        const float ISD = 0.17677669529663687f;          // 1/sqrt(32)
        const float SC[5] = {ISD, ISD * 0.57735026918962576f, ISD, ISD,
                             ISD * 0.70710678118654752f};
        __syncthreads();
#pragma unroll
        for (int q = 0; q < 4; q++)
#pragma unroll
            for (int k = 0; k < 5; k++)
                sh_w[(eg * 4 + q) * 320 + k * 64 + c] = acc[q][k] * SC[k];
        __syncthreads();
        for (int u = tid; u < ENT * 32; u += 256) {
            int el = u >> 5, lane = u & 31, cc = lane * 2;
            const float* row = sh_w + el * 320;
            __half2 p1 = __floats2half2_rn(row[0 * 64 + cc], row[0 * 64 + cc + 1]);
            __half2 p2 = __floats2half2_rn(row[1 * 64 + cc], row[1 * 64 + cc + 1]);
            __half2 p3 = __floats2half2_rn(row[2 * 64 + cc], row[2 * 64 + cc + 1]);
            __half2 p4 = __floats2half2_rn(row[3 * 64 + cc], row[3 * 64 + cc + 1]);
            __half2 p5 = __floats2half2_rn(row[4 * 64 + cc], row[4 * 64 + cc + 1]);
            size_t base = ((size_t)L * NTAB + e_blk + el) * 32 + lane;
            g_tV[base] = make_uint4(*(unsigned*)&p1, *(unsigned*)&p2,
                                    *(unsigned*)&p3, *(unsigned*)&p4);
            g_t5[base] = *(unsigned*)&p5;
        }
    } else {
        // ---- node feature init ----
        int i = (b - nEdgeBlk - nTabBlk) * 256 + tid;
        if (i < N * 192) g_v[i] = 0.f;
        if (i < N * 64) {
            int n = i >> 6, cc = i & 63;
            g_s[i] = w_lin_in[atom_type[n] * 64 + cc];
        }
        if (i < N * 32) {
            int n = i >> 5, l = i & 31;
            int t = atom_type[n];
            __half2 s2 = __floats2half2_rn(w_lin_in[t * 64 + 2 * l],
                                           w_lin_in[t * 64 + 2 * l + 1]);
            __half2 z2 = __floats2half2_rn(0.f, 0.f);
            uint4 f4;
            f4.x = *(unsigned*)&s2; f4.y = *(unsigned*)&z2;
            f4.z = *(unsigned*)&z2; f4.w = *(unsigned*)&z2;
            g_feat[i] = f4;
        }
    }
}

// ---------------- single-block exclusive scan ----------------
__global__ void k_scan(int N) {
    __shared__ int sm[1024];
    int tid = threadIdx.x;
    int per = (N + 1023) >> 10;
    int st = tid * per;
    int s = 0;
    for (int i = 0; i < per; i++) { int idx = st + i; if (idx < N) s += g_hist[idx]; }
    sm[tid] = s;
    __syncthreads();
    for (int d = 1; d < 1024; d <<= 1) {
        int v = (tid >= d) ? sm[tid - d] : 0;
        __syncthreads();
        sm[tid] += v;
        __syncthreads();
    }
    int pre = tid ? sm[tid - 1] : 0;
    for (int i = 0; i < per; i++) {
        int idx = st + i;
        if (idx < N) { g_off[idx] = pre; g_cur[idx] = pre; pre += g_hist[idx]; }
    }
    if (tid == 0) g_off[N] = sm[1023];
}

// -------- scatter into dst-sorted order; also re-zero g_hist for next replay --------
__global__ void k_scatter(const int* __restrict__ edst, int E, int N) {
    int e = blockIdx.x * blockDim.x + threadIdx.x;
    if (e < N) g_hist[e] = 0;
    if (e >= E) return;
    uint4 rec = g_ev[e];
    if (rec.w == 0xFFFFFFFFu) return;   // filtered
    int d = edst[e];
    int p = atomicAdd(&g_cur[d], 1);
    g_rec[p] = rec;
}

#define H2(u) (*(__half2*)&(u))

// per-edge message math in half2; accumulation folded into the fma chains
__device__ __forceinline__ void edge_acc(uint4 rc, uint4 qv, unsigned q5, uint4 ft,
                                         __half2& hS, __half2& hX,
                                         __half2& hY, __half2& hZ) {
    __half2 w1 = H2(qv.x), w2 = H2(qv.y), w3 = H2(qv.z), w4 = H2(qv.w), w5 = H2(q5);
    __half2 s01 = H2(ft.x), vx = H2(ft.y), vy = H2(ft.z), vz = H2(ft.w);
    __half2 yx2 = H2(rc.x), yy2 = H2(rc.y), yz2 = H2(rc.z);
    __half2 vd = __hfma2(vz, yz2, __hfma2(vy, yy2, __hmul2(vx, yx2)));
    hS = __hfma2(w1, s01, __hfma2(w2, vd, hS));
    __half2 t3 = __hmul2(w3, s01);
    __half2 cxh = __hfma2(__hneg2(vz), yy2, __hmul2(vy, yz2));
    __half2 cyh = __hfma2(__hneg2(vx), yz2, __hmul2(vz, yx2));
    __half2 czh = __hfma2(__hneg2(vy), yx2, __hmul2(vx, yy2));
    hX = __hfma2(w5, cxh, __hfma2(w4, vx, __hfma2(t3, yx2, hX)));
    hY = __hfma2(w5, cyh, __hfma2(w4, vy, __hfma2(t3, yy2, hY)));
    hZ = __hfma2(w5, czh, __hfma2(w4, vz, __hfma2(t3, yz2, hZ)));
}

// ------- main per-layer aggregate: TWO warps per dst atom (even/odd edges),
//         copy-free double-buffered pipeline, half2 math, fp32 flush per pair,
//         __launch_bounds__ forces 4 blocks/SM -------
__global__ void __launch_bounds__(256, 4) k_aggregate(int L, int N) {
    __shared__ float red[4][8][32];
    int tid = threadIdx.x;
    int lane = tid & 31;
    int warpInBlk = tid >> 5;
    int atomInBlk = warpInBlk >> 1;
    int half = warpInBlk & 1;
    int atom = blockIdx.x * 4 + atomInBlk;
    int valid = atom < N;
    int o0 = valid ? g_off[atom] : 0;
    int o1 = valid ? g_off[atom + 1] : 0;
    int c0 = lane << 1;
    float aS0 = 0, aS1 = 0, aX0 = 0, aX1 = 0, aY0 = 0, aY1 = 0, aZ0 = 0, aZ1 = 0;
    const uint4* tV = g_tV + (size_t)L * NTAB * 32;
    const unsigned* t5 = g_t5 + (size_t)L * NTAB * 32;
    const __half2 hz2 = __floats2half2_rn(0.f, 0.f);

    int p = o0 + half;                     // edges p, p+2, ...
    int m = o1 - p; m = m > 0 ? (m + 1) >> 1 : 0;   // # edges this warp

    if (m > 0) {
        // prologue — slot A (edge 0), slot B (edge 1), rec queue for edges 2,3
        uint4 recA = g_rec[p];
        int ibA = (int)(recA.w & 0xFFFu) * 32 + lane;
        uint4 qvA = tV[ibA]; unsigned q5A = t5[ibA];
        uint4 ftA = g_feat[(int)(recA.w >> 12) * 32 + lane];

        uint4 recB, qvB, ftB; unsigned q5B = 0;
        if (m > 1) {
            recB = g_rec[p + 2];
            int ibB = (int)(recB.w & 0xFFFu) * 32 + lane;
            qvB = tV[ibB]; q5B = t5[ibB];
            ftB = g_feat[(int)(recB.w >> 12) * 32 + lane];
        }
        uint4 recQ0 = g_rec[p + 4];   // edge 2 (garbage-safe: array has slack)
        uint4 recQ1 = g_rec[p + 6];   // edge 3

        int k = 0;
        // main loop: processes pair (k, k+1); requires edges k+2,k+3 valid for reload
        for (; k + 3 < m; k += 2) {
            __half2 hS = hz2, hX = hz2, hY = hz2, hZ = hz2;
            // edge k (slot A)
            edge_acc(recA, qvA, q5A, ftA, hS, hX, hY, hZ);
            recA = recQ0;                              // rec for edge k+2 (resident)
            {
                int ib = (int)(recA.w & 0xFFFu) * 32 + lane;
                qvA = tV[ib]; q5A = t5[ib];
                ftA = g_feat[(int)(recA.w >> 12) * 32 + lane];
            }
            recQ0 = g_rec[p + 2 * (k + 4)];            // rec for edge k+4
            // edge k+1 (slot B)
            edge_acc(recB, qvB, q5B, ftB, hS, hX, hY, hZ);
            recB = recQ1;                              // rec for edge k+3 (resident)
            {
                int ib = (int)(recB.w & 0xFFFu) * 32 + lane;
                qvB = tV[ib]; q5B = t5[ib];
                ftB = g_feat[(int)(recB.w >> 12) * 32 + lane];
            }
            recQ1 = g_rec[p + 2 * (k + 5)];            // rec for edge k+5
            // flush pair to fp32
            float2 f;
            f = __half22float2(hS); aS0 += f.x; aS1 += f.y;
            f = __half22float2(hX); aX0 += f.x; aX1 += f.y;
            f = __half22float2(hY); aY0 += f.x; aY1 += f.y;
            f = __half22float2(hZ); aZ0 += f.x; aZ1 += f.y;
        }
        // drain: at most edges k, k+1, k+2
        {
            __half2 hS = hz2, hX = hz2, hY = hz2, hZ = hz2;
            if (k < m)     edge_acc(recA, qvA, q5A, ftA, hS, hX, hY, hZ);
            if (k + 1 < m) edge_acc(recB, qvB, q5B, ftB, hS, hX, hY, hZ);
            if (k + 2 < m) {
                int ib = (int)(recQ0.w & 0xFFFu) * 32 + lane;
                uint4 qv = tV[ib];
                unsigned q5v = t5[ib];
                uint4 ft = g_feat[(int)(recQ0.w >> 12) * 32 + lane];
                edge_acc(recQ0, qv, q5v, ft, hS, hX, hY, hZ);
            }
            float2 f;
            f = __half22float2(hS); aS0 += f.x; aS1 += f.y;
            f = __half22float2(hX); aX0 += f.x; aX1 += f.y;
            f = __half22float2(hY); aY0 += f.x; aY1 += f.y;
            f = __half22float2(hZ); aZ0 += f.x; aZ1 += f.y;
        }
    }

    // cross-warp reduction (odd half -> smem, even half combines & writes)
    if (half) {
        red[atomInBlk][0][lane] = aS0; red[atomInBlk][1][lane] = aS1;
        red[atomInBlk][2][lane] = aX0; red[atomInBlk][3][lane] = aX1;
        red[atomInBlk][4][lane] = aY0; red[atomInBlk][5][lane] = aY1;
        red[atomInBlk][6][lane] = aZ0; red[atomInBlk][7][lane] = aZ1;
    }
    __syncthreads();
    if (!half && valid) {
        aS0 += red[atomInBlk][0][lane]; aS1 += red[atomInBlk][1][lane];
        aX0 += red[atomInBlk][2][lane]; aX1 += red[atomInBlk][3][lane];
        aY0 += red[atomInBlk][4][lane]; aY1 += red[atomInBlk][5][lane];
        aZ0 += red[atomInBlk][6][lane]; aZ1 += red[atomInBlk][7][lane];
        *(float2*)(g_as + atom * 64 + c0) = make_float2(aS0, aS1);
        float* ov = g_av + atom * 192 + c0;
        *(float2*)(ov) = make_float2(aX0, aX1);
        *(float2*)(ov + 64) = make_float2(aY0, aY1);
        *(float2*)(ov + 128) = make_float2(aZ0, aZ1);
    }
}

// ---- node self-interaction + resnet (+feat mirror); 4 atoms per warp ----
__global__ void k_node(int L, int N, const float* __restrict__ wss,
                       const float* __restrict__ wsv,
                       const float* __restrict__ wgt) {
    __shared__ float sWs[4096];
    __shared__ float sWv[4096];
    __shared__ float sWg[4096];
    const float* ps = wss + (size_t)L * 4096;
    const float* pv = wsv + (size_t)L * 4096;
    const float* pg = wgt + (size_t)L * 4096;
    for (int i = threadIdx.x; i < 4096; i += blockDim.x) {
        sWs[i] = ps[i]; sWv[i] = pv[i]; sWg[i] = pg[i];
    }
    __syncthreads();
    int lane = threadIdx.x & 31;
    int c0 = lane << 1;
    int baseAtom = blockIdx.x * 32 + (threadIdx.x >> 5) * 4;
    for (int a = 0; a < 4; a++) {
        int gw = baseAtom + a;
        if (gw >= N) break;
        float2 aa = *(const float2*)(g_as + gw * 64 + c0);
        const float* avp = g_av + gw * 192 + c0;
        float2 ax = *(const float2*)(avp);
        float2 ay = *(const float2*)(avp + 64);
        float2 az = *(const float2*)(avp + 128);
        float gs0 = 0, gs1 = 0, t0 = 0, t1 = 0;
        float vx0 = 0, vx1 = 0, vy0 = 0, vy1 = 0, vz0 = 0, vz1 = 0;
#pragma unroll
        for (int j = 0; j < 64; j++) {
            int sl = j >> 1;
            float aj = __shfl_sync(0xffffffffu, (j & 1) ? aa.y : aa.x, sl);
            float jx = __shfl_sync(0xffffffffu, (j & 1) ? ax.y : ax.x, sl);
            float jy = __shfl_sync(0xffffffffu, (j & 1) ? ay.y : ay.x, sl);
            float jz = __shfl_sync(0xffffffffu, (j & 1) ? az.y : az.x, sl);
            float2 wg2 = *(const float2*)(sWg + j * 64 + c0);
            float2 ws2 = *(const float2*)(sWs + j * 64 + c0);
            float2 wv2 = *(const float2*)(sWv + j * 64 + c0);
            gs0 += aj * wg2.x; gs1 += aj * wg2.y;
            t0 += aj * ws2.x;  t1 += aj * ws2.y;
            vx0 += jx * wv2.x; vx1 += jx * wv2.y;
            vy0 += jy * wv2.x; vy1 += jy * wv2.y;
            vz0 += jz * wv2.x; vz1 += jz * wv2.y;
        }
        float g0 = 1.f / (1.f + expf(-gs0));
        float g1 = 1.f / (1.f + expf(-gs1));
        float si0 = t0 / (1.f + expf(-t0));
        float si1 = t1 / (1.f + expf(-t1));
        float* sp = g_s + gw * 64 + c0;
        float2 sv = *(float2*)sp;
        sv.x += si0; sv.y += si1;
        *(float2*)sp = sv;
        float* vp = g_v + gw * 192 + c0;
        float2 v1, v2, v3;
        v1 = *(float2*)(vp);       v1.x += vx0 * g0; v1.y += vx1 * g1; *(float2*)(vp) = v1;
        v2 = *(float2*)(vp + 64);  v2.x += vy0 * g0; v2.y += vy1 * g1; *(float2*)(vp + 64) = v2;
        v3 = *(float2*)(vp + 128); v3.x += vz0 * g0; v3.y += vz1 * g1; *(float2*)(vp + 128) = v3;
        __half2 hs = __floats2half2_rn(sv.x, sv.y);
        __half2 h1 = __floats2half2_rn(v1.x, v1.y);
        __half2 h2 = __floats2half2_rn(v2.x, v2.y);
        __half2 h3 = __floats2half2_rn(v3.x, v3.y);
        uint4 f4;
        f4.x = *(unsigned*)&hs; f4.y = *(unsigned*)&h1;
        f4.z = *(unsigned*)&h2; f4.w = *(unsigned*)&h3;
        g_feat[gw * 32 + lane] = f4;
    }
}

// ---------------- final energy head ----------------
__global__ void k_energy(int N, const float* __restrict__ wl1,
                         const float* __restrict__ wl2,
                         float* __restrict__ out) {
    __shared__ float sW[1024];
    __shared__ float sw2[16];
    for (int i = threadIdx.x; i < 1024; i += blockDim.x) sW[i] = wl1[i];
    if (threadIdx.x < 16) sw2[threadIdx.x] = wl2[threadIdx.x];
    __syncthreads();
    int gw = blockIdx.x * 8 + (threadIdx.x >> 5);
    if (gw >= N) return;
    int lane = threadIdx.x & 31;
    int c0 = lane << 1;
    float2 s = *(const float2*)(g_s + gw * 64 + c0);
    float p[16];
#pragma unroll
    for (int k = 0; k < 16; k++)
        p[k] = s.x * sW[c0 * 16 + k] + s.y * sW[(c0 + 1) * 16 + k];
#pragma unroll
    for (int d = 16; d >= 1; d >>= 1) {
#pragma unroll
        for (int k = 0; k < 16; k++) p[k] += __shfl_down_sync(0xffffffffu, p[k], d);
    }
    if (lane == 0) {
        float e = 0.f;
#pragma unroll
        for (int k = 0; k < 16; k++) e += p[k] * sw2[k];
        out[gw] = e;
    }
}

// ---------------- launch ----------------
extern "C" void kernel_launch(void* const* d_in, const int* in_sizes, int n_in,
                              void* d_out, int out_size) {
    const int*   atom_type = (const int*)d_in[0];
    const float* atom_pos  = (const float*)d_in[1];
    const int*   edge_src  = (const int*)d_in[2];
    const int*   edge_dst  = (const int*)d_in[3];
    const float* shift     = (const float*)d_in[4];
    const float* cell      = (const float*)d_in[5];
    const int*   image_idx = (const int*)d_in[6];
    const float* w_lin_in  = (const float*)d_in[7];
    const float* mw1       = (const float*)d_in[8];
    const float* mb1       = (const float*)d_in[9];
    const float* mw2       = (const float*)d_in[10];
    const float* wss       = (const float*)d_in[11];
    const float* wsv       = (const float*)d_in[12];
    const float* wgt       = (const float*)d_in[13];
    const float* wl1       = (const float*)d_in[14];
    const float* wl2       = (const float*)d_in[15];
    int N = in_sizes[0];
    int E = in_sizes[2];
    float* out = (float*)d_out;

    int nEdgeBlk = (E + 255) / 256;
    int nTabBlk  = NLAYERS * (NTAB / ENT);
    int nInitBlk = (N * 192 + 255) / 256;

    k_mega<<<nEdgeBlk + nTabBlk + nInitBlk, 256>>>(
        atom_pos, edge_src, edge_dst, shift, cell, image_idx,
        atom_type, w_lin_in, mw1, mb1, mw2, E, N, nEdgeBlk, nTabBlk);
    k_scan<<<1, 1024>>>(N);
    k_scatter<<<(E + 255) / 256, 256>>>(edge_dst, E, N);
    for (int L = 0; L < NLAYERS; ++L) {
        k_aggregate<<<(N + 3) / 4, 256>>>(L, N);
        k_node<<<(N + 31) / 32, 256>>>(L, N, wss, wsv, wgt);
    }
    k_energy<<<(N + 7) / 8, 256>>>(N, wl1, wl2, out);
}

// round 16
// speedup vs baseline: 1.1453x; 1.0246x over previous
#include <cuda_runtime.h>
#include <cuda_fp16.h>
#include <math.h>

#define MAXN 16384
#define MAXE 524288
#define NTAB 4096
#define RMAXF 5.0f
#define NLAYERS 3
#define ENT 16
#define JT 16

// ---------------- static scratch (no allocation allowed) ----------------
__device__ uint4     g_ev[MAXE];        // unsorted: {yx h2, yy h2, yz h2, (ty<<26)|(src<<12)|i0}
__device__ uint4     g_rec[MAXE];       // dst-sorted records (same format)
__device__ int       g_hist[MAXN];      // zeroed by k_scatter for next replay
__device__ int       g_cur[MAXN];
__device__ int       g_off[MAXN + 1];
// nearest-entry half tables per lane: vals paths1-4 (16B), val path5 (4B)
__device__ uint4     g_tV[NLAYERS * NTAB * 32];
__device__ unsigned  g_t5[NLAYERS * NTAB * 32];
__device__ float     g_s[MAXN * 64];
__device__ float     g_v[MAXN * 192];   // layout [n][3][64]
__device__ float     g_as[MAXN * 64];
__device__ float     g_av[MAXN * 192];
__device__ uint4     g_feat[MAXN * 32]; // per lane: {s h2, vx h2, vy h2, vz h2}
__device__ uint4     g_s0tab[32];       // per lane: s-half2 for atom types 0..3

// ================= mega kernel: edge_pre | table build | init =================
__global__ void k_mega(const float* __restrict__ pos,
                       const int* __restrict__ esrc,
                       const int* __restrict__ edst,
                       const float* __restrict__ shift,
                       const float* __restrict__ cell,
                       const int* __restrict__ img,
                       const int* __restrict__ atom_type,
                       const float* __restrict__ w_lin_in,
                       const float* __restrict__ mw1,
                       const float* __restrict__ mb1,
                       const float* __restrict__ mw2,
                       int E, int N, int nEdgeBlk, int nTabBlk) {
    __shared__ float sh_h[ENT * 64];   // 4KB  (table branch)
    __shared__ float sh_w[JT * 320];   // 20KB (table branch)
    int b = blockIdx.x;
    int tid = threadIdx.x;

    if (b < nEdgeBlk) {
        // ---- edge preprocess ----
        int e = b * 256 + tid;
        if (e >= E) return;
        int s = esrc[e], d = edst[e];
        float vx = pos[d * 3 + 0] - pos[s * 3 + 0];
        float vy = pos[d * 3 + 1] - pos[s * 3 + 1];
        float vz = pos[d * 3 + 2] - pos[s * 3 + 2];
        float s0 = shift[e * 3 + 0], s1 = shift[e * 3 + 1], s2 = shift[e * 3 + 2];
        const float* Cm = cell + img[s] * 9;
        vx += s0 * Cm[0] + s1 * Cm[3] + s2 * Cm[6];
        vy += s0 * Cm[1] + s1 * Cm[4] + s2 * Cm[7];
        vz += s0 * Cm[2] + s1 * Cm[5] + s2 * Cm[8];
        float r = sqrtf(vx * vx + vy * vy + vz * vz);
        uint4 rec;
        if (r < RMAXF) {
            float inv = 1.7320508075688772f / fmaxf(r, 1e-9f);  // sqrt3 * unit
            __half2 hx = __half2half2(__float2half_rn(vx * inv));
            __half2 hy = __half2half2(__float2half_rn(vy * inv));
            __half2 hz = __half2half2(__float2half_rn(vz * inv));
            int i0 = __float2int_rn(r * ((float)(NTAB - 1) / RMAXF));
            if (i0 > NTAB - 1) i0 = NTAB - 1;
            unsigned ty = (unsigned)atom_type[s];
            rec.x = *(unsigned*)&hx; rec.y = *(unsigned*)&hy;
            rec.z = *(unsigned*)&hz;
            rec.w = (ty << 26) | ((unsigned)s << 12) | (unsigned)i0;
            atomicAdd(&g_hist[d], 1);
        } else {
            rec.x = rec.y = rec.z = 0;
            rec.w = 0xFFFFFFFFu;   // filtered marker
        }
        g_ev[e] = rec;
    } else if (b < nEdgeBlk + nTabBlk) {
        // ---- fused table build: h in-block, GEMM, pack ----
        int tb = b - nEdgeBlk;
        int L = tb / (NTAB / ENT);
        int e_blk = (tb % (NTAB / ENT)) * ENT;
        for (int i = tid; i < ENT * 64; i += 256) {
            int el = i >> 6, t = i & 63;
            int entry = e_blk + el;
            float r = (float)entry * (RMAXF / (float)(NTAB - 1));
            float rs = fmaxf(r, 1e-9f);
            float x = r / RMAXF;
            float x2 = x * x;
            float x6 = x2 * x2 * x2;
            float fc = 1.f - 28.f * x6 + 48.f * x6 * x - 21.f * x6 * x2;
            if (x >= 1.f) fc = 0.f;
            float cscale = sqrtf(2.f / RMAXF) * fc / rs;
            float arg = 3.14159265358979323846f * rs / RMAXF;
            float h = mb1[L * 64 + t];
#pragma unroll
            for (int j = 0; j < 8; j++)
                h += cscale * sinf((float)(j + 1) * arg) * mw1[(L * 8 + j) * 64 + t];
            sh_h[i] = h / (1.f + expf(-h));  // silu
        }

        int c = tid & 63;
        int eg = tid >> 6;
        float acc[4][5];
#pragma unroll
        for (int q = 0; q < 4; q++)
#pragma unroll
            for (int k = 0; k < 5; k++) acc[q][k] = 0.f;

        for (int j0 = 0; j0 < 64; j0 += JT) {
            __syncthreads();
            const float* wsrc = mw2 + ((size_t)L * 64 + j0) * 320;
            for (int i = tid; i < JT * 320; i += 256) sh_w[i] = wsrc[i];
            __syncthreads();
#pragma unroll
            for (int j = 0; j < JT; j++) {
                float w0 = sh_w[j * 320 + 0 * 64 + c];
                float w1 = sh_w[j * 320 + 1 * 64 + c];
                float w2 = sh_w[j * 320 + 2 * 64 + c];
                float w3 = sh_w[j * 320 + 3 * 64 + c];
                float w4 = sh_w[j * 320 + 4 * 64 + c];
#pragma unroll
                for (int q = 0; q < 4; q++) {
                    float hj = sh_h[(eg * 4 + q) * 64 + j0 + j];
                    acc[q][0] += hj * w0;
                    acc[q][1] += hj * w1;
                    acc[q][2] += hj * w2;
                    acc[q][3] += hj * w3;
                    acc[q][4] += hj * w4;
                }
            }
        }
        const float ISD = 0.17677669529663687f;          // 1/sqrt(32)
        const float SC[5] = {ISD, ISD * 0.57735026918962576f, ISD, ISD,
                             ISD * 0.70710678118654752f};
        __syncthreads();
#pragma unroll
        for (int q = 0; q < 4; q++)
#pragma unroll
            for (int k = 0; k < 5; k++)
                sh_w[(eg * 4 + q) * 320 + k * 64 + c] = acc[q][k] * SC[k];
        __syncthreads();
        for (int u = tid; u < ENT * 32; u += 256) {
            int el = u >> 5, lane = u & 31, cc = lane * 2;
            const float* row = sh_w + el * 320;
            __half2 p1 = __floats2half2_rn(row[0 * 64 + cc], row[0 * 64 + cc + 1]);
            __half2 p2 = __floats2half2_rn(row[1 * 64 + cc], row[1 * 64 + cc + 1]);
            __half2 p3 = __floats2half2_rn(row[2 * 64 + cc], row[2 * 64 + cc + 1]);
            __half2 p4 = __floats2half2_rn(row[3 * 64 + cc], row[3 * 64 + cc + 1]);
            __half2 p5 = __floats2half2_rn(row[4 * 64 + cc], row[4 * 64 + cc + 1]);
            size_t base = ((size_t)L * NTAB + e_blk + el) * 32 + lane;
            g_tV[base] = make_uint4(*(unsigned*)&p1, *(unsigned*)&p2,
                                    *(unsigned*)&p3, *(unsigned*)&p4);
            g_t5[base] = *(unsigned*)&p5;
        }
    } else {
        // ---- node feature init ----
        int i = (b - nEdgeBlk - nTabBlk) * 256 + tid;
        if (i < N * 192) g_v[i] = 0.f;
        if (i < N * 64) {
            int n = i >> 6, cc = i & 63;
            g_s[i] = w_lin_in[atom_type[n] * 64 + cc];
        }
        if (i < N * 32) {
            int n = i >> 5, l = i & 31;
            int t = atom_type[n];
            __half2 s2 = __floats2half2_rn(w_lin_in[t * 64 + 2 * l],
                                           w_lin_in[t * 64 + 2 * l + 1]);
            __half2 z2 = __floats2half2_rn(0.f, 0.f);
            uint4 f4;
            f4.x = *(unsigned*)&s2; f4.y = *(unsigned*)&z2;
            f4.z = *(unsigned*)&z2; f4.w = *(unsigned*)&z2;
            g_feat[i] = f4;
        }
        if (i < 32) {
            // per-lane type table for layer-0 aggregate
            unsigned pk[4];
#pragma unroll
            for (int t = 0; t < 4; t++) {
                __half2 h = __floats2half2_rn(w_lin_in[t * 64 + 2 * i],
                                              w_lin_in[t * 64 + 2 * i + 1]);
                pk[t] = *(unsigned*)&h;
            }
            g_s0tab[i] = make_uint4(pk[0], pk[1], pk[2], pk[3]);
        }
    }
}

// ---------------- single-block exclusive scan ----------------
__global__ void k_scan(int N) {
    __shared__ int sm[1024];
    int tid = threadIdx.x;
    int per = (N + 1023) >> 10;
    int st = tid * per;
    int s = 0;
    for (int i = 0; i < per; i++) { int idx = st + i; if (idx < N) s += g_hist[idx]; }
    sm[tid] = s;
    __syncthreads();
    for (int d = 1; d < 1024; d <<= 1) {
        int v = (tid >= d) ? sm[tid - d] : 0;
        __syncthreads();
        sm[tid] += v;
        __syncthreads();
    }
    int pre = tid ? sm[tid - 1] : 0;
    for (int i = 0; i < per; i++) {
        int idx = st + i;
        if (idx < N) { g_off[idx] = pre; g_cur[idx] = pre; pre += g_hist[idx]; }
    }
    if (tid == 0) g_off[N] = sm[1023];
}

// -------- scatter into dst-sorted order; also re-zero g_hist for next replay --------
__global__ void k_scatter(const int* __restrict__ edst, int E, int N) {
    int e = blockIdx.x * blockDim.x + threadIdx.x;
    if (e < N) g_hist[e] = 0;
    if (e >= E) return;
    uint4 rec = g_ev[e];
    if (rec.w == 0xFFFFFFFFu) return;   // filtered
    int d = edst[e];
    int p = atomicAdd(&g_cur[d], 1);
    g_rec[p] = rec;
}

#define H2(u) (*(__half2*)&(u))

// per-edge message math in half2; accumulation folded into the fma chains
__device__ __forceinline__ void edge_acc(uint4 rc, uint4 qv, unsigned q5, uint4 ft,
                                         __half2& hS, __half2& hX,
                                         __half2& hY, __half2& hZ) {
    __half2 w1 = H2(qv.x), w2 = H2(qv.y), w3 = H2(qv.z), w4 = H2(qv.w), w5 = H2(q5);
    __half2 s01 = H2(ft.x), vx = H2(ft.y), vy = H2(ft.z), vz = H2(ft.w);
    __half2 yx2 = H2(rc.x), yy2 = H2(rc.y), yz2 = H2(rc.z);
    __half2 vd = __hfma2(vz, yz2, __hfma2(vy, yy2, __hmul2(vx, yx2)));
    hS = __hfma2(w1, s01, __hfma2(w2, vd, hS));
    __half2 t3 = __hmul2(w3, s01);
    __half2 cxh = __hfma2(__hneg2(vz), yy2, __hmul2(vy, yz2));
    __half2 cyh = __hfma2(__hneg2(vx), yz2, __hmul2(vz, yx2));
    __half2 czh = __hfma2(__hneg2(vy), yx2, __hmul2(vx, yy2));
    hX = __hfma2(w5, cxh, __hfma2(w4, vx, __hfma2(t3, yx2, hX)));
    hY = __hfma2(w5, cyh, __hfma2(w4, vy, __hfma2(t3, yy2, hY)));
    hZ = __hfma2(w5, czh, __hfma2(w4, vz, __hfma2(t3, yz2, hZ)));
}

// layer-0 message: v=0, s from type table -> only paths 1 and 3 survive
__device__ __forceinline__ void edge_acc0(uint4 rc, uint4 qv, uint4 st,
                                          __half2& hS, __half2& hX,
                                          __half2& hY, __half2& hZ) {
    unsigned ty = rc.w >> 26;
    unsigned su = (ty & 2u) ? ((ty & 1u) ? st.w : st.z)
                            : ((ty & 1u) ? st.y : st.x);
    __half2 s01 = H2(su);
    __half2 w1 = H2(qv.x), w3 = H2(qv.z);
    __half2 yx2 = H2(rc.x), yy2 = H2(rc.y), yz2 = H2(rc.z);
    hS = __hfma2(w1, s01, hS);
    __half2 t3 = __hmul2(w3, s01);
    hX = __hfma2(t3, yx2, hX);
    hY = __hfma2(t3, yy2, hY);
    hZ = __hfma2(t3, yz2, hZ);
}

// ------- general-layer aggregate (L=1,2): copy-free double-buffered pipeline -------
__global__ void __launch_bounds__(256, 4) k_aggregate(int L, int N) {
    __shared__ float red[4][8][32];
    int tid = threadIdx.x;
    int lane = tid & 31;
    int warpInBlk = tid >> 5;
    int atomInBlk = warpInBlk >> 1;
    int half = warpInBlk & 1;
    int atom = blockIdx.x * 4 + atomInBlk;
    int valid = atom < N;
    int o0 = valid ? g_off[atom] : 0;
    int o1 = valid ? g_off[atom + 1] : 0;
    int c0 = lane << 1;
    float aS0 = 0, aS1 = 0, aX0 = 0, aX1 = 0, aY0 = 0, aY1 = 0, aZ0 = 0, aZ1 = 0;
    const uint4* tV = g_tV + (size_t)L * NTAB * 32;
    const unsigned* t5 = g_t5 + (size_t)L * NTAB * 32;
    const __half2 hz2 = __floats2half2_rn(0.f, 0.f);

    int p = o0 + half;                     // edges p, p+2, ...
    int m = o1 - p; m = m > 0 ? (m + 1) >> 1 : 0;   // # edges this warp

    if (m > 0) {
        uint4 recA = g_rec[p];
        int ibA = (int)(recA.w & 0xFFFu) * 32 + lane;
        uint4 qvA = tV[ibA]; unsigned q5A = t5[ibA];
        uint4 ftA = g_feat[(int)((recA.w >> 12) & 0x3FFFu) * 32 + lane];

        uint4 recB, qvB, ftB; unsigned q5B = 0;
        if (m > 1) {
            recB = g_rec[p + 2];
            int ibB = (int)(recB.w & 0xFFFu) * 32 + lane;
            qvB = tV[ibB]; q5B = t5[ibB];
            ftB = g_feat[(int)((recB.w >> 12) & 0x3FFFu) * 32 + lane];
        }
        uint4 recQ0 = g_rec[p + 4];
        uint4 recQ1 = g_rec[p + 6];

        int k = 0;
        for (; k + 3 < m; k += 2) {
            __half2 hS = hz2, hX = hz2, hY = hz2, hZ = hz2;
            edge_acc(recA, qvA, q5A, ftA, hS, hX, hY, hZ);
            recA = recQ0;
            {
                int ib = (int)(recA.w & 0xFFFu) * 32 + lane;
                qvA = tV[ib]; q5A = t5[ib];
                ftA = g_feat[(int)((recA.w >> 12) & 0x3FFFu) * 32 + lane];
            }
            recQ0 = g_rec[p + 2 * (k + 4)];
            edge_acc(recB, qvB, q5B, ftB, hS, hX, hY, hZ);
            recB = recQ1;
            {
                int ib = (int)(recB.w & 0xFFFu) * 32 + lane;
                qvB = tV[ib]; q5B = t5[ib];
                ftB = g_feat[(int)((recB.w >> 12) & 0x3FFFu) * 32 + lane];
            }
            recQ1 = g_rec[p + 2 * (k + 5)];
            float2 f;
            f = __half22float2(hS); aS0 += f.x; aS1 += f.y;
            f = __half22float2(hX); aX0 += f.x; aX1 += f.y;
            f = __half22float2(hY); aY0 += f.x; aY1 += f.y;
            f = __half22float2(hZ); aZ0 += f.x; aZ1 += f.y;
        }
        {
            __half2 hS = hz2, hX = hz2, hY = hz2, hZ = hz2;
            if (k < m)     edge_acc(recA, qvA, q5A, ftA, hS, hX, hY, hZ);
            if (k + 1 < m) edge_acc(recB, qvB, q5B, ftB, hS, hX, hY, hZ);
            if (k + 2 < m) {
                int ib = (int)(recQ0.w & 0xFFFu) * 32 + lane;
                uint4 qv = tV[ib];
                unsigned q5v = t5[ib];
                uint4 ft = g_feat[(int)((recQ0.w >> 12) & 0x3FFFu) * 32 + lane];
                edge_acc(recQ0, qv, q5v, ft, hS, hX, hY, hZ);
            }
            float2 f;
            f = __half22float2(hS); aS0 += f.x; aS1 += f.y;
            f = __half22float2(hX); aX0 += f.x; aX1 += f.y;
            f = __half22float2(hY); aY0 += f.x; aY1 += f.y;
            f = __half22float2(hZ); aZ0 += f.x; aZ1 += f.y;
        }
    }

    if (half) {
        red[atomInBlk][0][lane] = aS0; red[atomInBlk][1][lane] = aS1;
        red[atomInBlk][2][lane] = aX0; red[atomInBlk][3][lane] = aX1;
        red[atomInBlk][4][lane] = aY0; red[atomInBlk][5][lane] = aY1;
        red[atomInBlk][6][lane] = aZ0; red[atomInBlk][7][lane] = aZ1;
    }
    __syncthreads();
    if (!half && valid) {
        aS0 += red[atomInBlk][0][lane]; aS1 += red[atomInBlk][1][lane];
        aX0 += red[atomInBlk][2][lane]; aX1 += red[atomInBlk][3][lane];
        aY0 += red[atomInBlk][4][lane]; aY1 += red[atomInBlk][5][lane];
        aZ0 += red[atomInBlk][6][lane]; aZ1 += red[atomInBlk][7][lane];
        *(float2*)(g_as + atom * 64 + c0) = make_float2(aS0, aS1);
        float* ov = g_av + atom * 192 + c0;
        *(float2*)(ov) = make_float2(aX0, aX1);
        *(float2*)(ov + 64) = make_float2(aY0, aY1);
        *(float2*)(ov + 128) = make_float2(aZ0, aZ1);
    }
}

// ------- layer-0 aggregate: no feature gather, type-indexed s, 2 loads/edge -------
__global__ void __launch_bounds__(256, 4) k_aggregate0(int N) {
    __shared__ float red[4][8][32];
    int tid = threadIdx.x;
    int lane = tid & 31;
    int warpInBlk = tid >> 5;
    int atomInBlk = warpInBlk >> 1;
    int half = warpInBlk & 1;
    int atom = blockIdx.x * 4 + atomInBlk;
    int valid = atom < N;
    int o0 = valid ? g_off[atom] : 0;
    int o1 = valid ? g_off[atom + 1] : 0;
    int c0 = lane << 1;
    float aS0 = 0, aS1 = 0, aX0 = 0, aX1 = 0, aY0 = 0, aY1 = 0, aZ0 = 0, aZ1 = 0;
    const uint4* tV = g_tV;   // layer 0
    const uint4 st = g_s0tab[lane];
    const __half2 hz2 = __floats2half2_rn(0.f, 0.f);

    int p = o0 + half;
    int m = o1 - p; m = m > 0 ? (m + 1) >> 1 : 0;

    if (m > 0) {
        uint4 recA = g_rec[p];
        uint4 qvA = tV[(int)(recA.w & 0xFFFu) * 32 + lane];
        uint4 recB, qvB;
        if (m > 1) {
            recB = g_rec[p + 2];
            qvB = tV[(int)(recB.w & 0xFFFu) * 32 + lane];
        }
        uint4 recQ0 = g_rec[p + 4];
        uint4 recQ1 = g_rec[p + 6];

        int k = 0;
        for (; k + 3 < m; k += 2) {
            __half2 hS = hz2, hX = hz2, hY = hz2, hZ = hz2;
            edge_acc0(recA, qvA, st, hS, hX, hY, hZ);
            recA = recQ0;
            qvA = tV[(int)(recA.w & 0xFFFu) * 32 + lane];
            recQ0 = g_rec[p + 2 * (k + 4)];
            edge_acc0(recB, qvB, st, hS, hX, hY, hZ);
            recB = recQ1;
            qvB = tV[(int)(recB.w & 0xFFFu) * 32 + lane];
            recQ1 = g_rec[p + 2 * (k + 5)];
            float2 f;
            f = __half22float2(hS); aS0 += f.x; aS1 += f.y;
            f = __half22float2(hX); aX0 += f.x; aX1 += f.y;
            f = __half22float2(hY); aY0 += f.x; aY1 += f.y;
            f = __half22float2(hZ); aZ0 += f.x; aZ1 += f.y;
        }
        {
            __half2 hS = hz2, hX = hz2, hY = hz2, hZ = hz2;
            if (k < m)     edge_acc0(recA, qvA, st, hS, hX, hY, hZ);
            if (k + 1 < m) edge_acc0(recB, qvB, st, hS, hX, hY, hZ);
            if (k + 2 < m) {
                uint4 qv = tV[(int)(recQ0.w & 0xFFFu) * 32 + lane];
                edge_acc0(recQ0, qv, st, hS, hX, hY, hZ);
            }
            float2 f;
            f = __half22float2(hS); aS0 += f.x; aS1 += f.y;
            f = __half22float2(hX); aX0 += f.x; aX1 += f.y;
            f = __half22float2(hY); aY0 += f.x; aY1 += f.y;
            f = __half22float2(hZ); aZ0 += f.x; aZ1 += f.y;
        }
    }

    if (half) {
        red[atomInBlk][0][lane] = aS0; red[atomInBlk][1][lane] = aS1;
        red[atomInBlk][2][lane] = aX0; red[atomInBlk][3][lane] = aX1;
        red[atomInBlk][4][lane] = aY0; red[atomInBlk][5][lane] = aY1;
        red[atomInBlk][6][lane] = aZ0; red[atomInBlk][7][lane] = aZ1;
    }
    __syncthreads();
    if (!half && valid) {
        aS0 += red[atomInBlk][0][lane]; aS1 += red[atomInBlk][1][lane];
        aX0 += red[atomInBlk][2][lane]; aX1 += red[atomInBlk][3][lane];
        aY0 += red[atomInBlk][4][lane]; aY1 += red[atomInBlk][5][lane];
        aZ0 += red[atomInBlk][6][lane]; aZ1 += red[atomInBlk][7][lane];
        *(float2*)(g_as + atom * 64 + c0) = make_float2(aS0, aS1);
        float* ov = g_av + atom * 192 + c0;
        *(float2*)(ov) = make_float2(aX0, aX1);
        *(float2*)(ov + 64) = make_float2(aY0, aY1);
        *(float2*)(ov + 128) = make_float2(aZ0, aZ1);
    }
}

// ---- node self-interaction + resnet (+feat mirror); 4 atoms per warp ----
__global__ void k_node(int L, int N, const float* __restrict__ wss,
                       const float* __restrict__ wsv,
                       const float* __restrict__ wgt) {
    __shared__ float sWs[4096];
    __shared__ float sWv[4096];
    __shared__ float sWg[4096];
    const float* ps = wss + (size_t)L * 4096;
    const float* pv = wsv + (size_t)L * 4096;
    const float* pg = wgt + (size_t)L * 4096;
    for (int i = threadIdx.x; i < 4096; i += blockDim.x) {
        sWs[i] = ps[i]; sWv[i] = pv[i]; sWg[i] = pg[i];
    }
    __syncthreads();
    int lane = threadIdx.x & 31;
    int c0 = lane << 1;
    int baseAtom = blockIdx.x * 32 + (threadIdx.x >> 5) * 4;
    for (int a = 0; a < 4; a++) {
        int gw = baseAtom + a;
        if (gw >= N) break;
        float2 aa = *(const float2*)(g_as + gw * 64 + c0);
        const float* avp = g_av + gw * 192 + c0;
        float2 ax = *(const float2*)(avp);
        float2 ay = *(const float2*)(avp + 64);
        float2 az = *(const float2*)(avp + 128);
        float gs0 = 0, gs1 = 0, t0 = 0, t1 = 0;
        float vx0 = 0, vx1 = 0, vy0 = 0, vy1 = 0, vz0 = 0, vz1 = 0;
#pragma unroll
        for (int j = 0; j < 64; j++) {
            int sl = j >> 1;
            float aj = __shfl_sync(0xffffffffu, (j & 1) ? aa.y : aa.x, sl);
            float jx = __shfl_sync(0xffffffffu, (j & 1) ? ax.y : ax.x, sl);
            float jy = __shfl_sync(0xffffffffu, (j & 1) ? ay.y : ay.x, sl);
            float jz = __shfl_sync(0xffffffffu, (j & 1) ? az.y : az.x, sl);
            float2 wg2 = *(const float2*)(sWg + j * 64 + c0);
            float2 ws2 = *(const float2*)(sWs + j * 64 + c0);
            float2 wv2 = *(const float2*)(sWv + j * 64 + c0);
            gs0 += aj * wg2.x; gs1 += aj * wg2.y;
            t0 += aj * ws2.x;  t1 += aj * ws2.y;
            vx0 += jx * wv2.x; vx1 += jx * wv2.y;
            vy0 += jy * wv2.x; vy1 += jy * wv2.y;
            vz0 += jz * wv2.x; vz1 += jz * wv2.y;
        }
        float g0 = 1.f / (1.f + expf(-gs0));
        float g1 = 1.f / (1.f + expf(-gs1));
        float si0 = t0 / (1.f + expf(-t0));
        float si1 = t1 / (1.f + expf(-t1));
        float* sp = g_s + gw * 64 + c0;
        float2 sv = *(float2*)sp;
        sv.x += si0; sv.y += si1;
        *(float2*)sp = sv;
        float* vp = g_v + gw * 192 + c0;
        float2 v1, v2, v3;
        v1 = *(float2*)(vp);       v1.x += vx0 * g0; v1.y += vx1 * g1; *(float2*)(vp) = v1;
        v2 = *(float2*)(vp + 64);  v2.x += vy0 * g0; v2.y += vy1 * g1; *(float2*)(vp + 64) = v2;
        v3 = *(float2*)(vp + 128); v3.x += vz0 * g0; v3.y += vz1 * g1; *(float2*)(vp + 128) = v3;
        __half2 hs = __floats2half2_rn(sv.x, sv.y);
        __half2 h1 = __floats2half2_rn(v1.x, v1.y);
        __half2 h2 = __floats2half2_rn(v2.x, v2.y);
        __half2 h3 = __floats2half2_rn(v3.x, v3.y);
        uint4 f4;
        f4.x = *(unsigned*)&hs; f4.y = *(unsigned*)&h1;
        f4.z = *(unsigned*)&h2; f4.w = *(unsigned*)&h3;
        g_feat[gw * 32 + lane] = f4;
    }
}

// ---------------- final energy head ----------------
__global__ void k_energy(int N, const float* __restrict__ wl1,
                         const float* __restrict__ wl2,
                         float* __restrict__ out) {
    __shared__ float sW[1024];
    __shared__ float sw2[16];
    for (int i = threadIdx.x; i < 1024; i += blockDim.x) sW[i] = wl1[i];
    if (threadIdx.x < 16) sw2[threadIdx.x] = wl2[threadIdx.x];
    __syncthreads();
    int gw = blockIdx.x * 8 + (threadIdx.x >> 5);
    if (gw >= N) return;
    int lane = threadIdx.x & 31;
    int c0 = lane << 1;
    float2 s = *(const float2*)(g_s + gw * 64 + c0);
    float p[16];
#pragma unroll
    for (int k = 0; k < 16; k++)
        p[k] = s.x * sW[c0 * 16 + k] + s.y * sW[(c0 + 1) * 16 + k];
#pragma unroll
    for (int d = 16; d >= 1; d >>= 1) {
#pragma unroll
        for (int k = 0; k < 16; k++) p[k] += __shfl_down_sync(0xffffffffu, p[k], d);
    }
    if (lane == 0) {
        float e = 0.f;
#pragma unroll
        for (int k = 0; k < 16; k++) e += p[k] * sw2[k];
        out[gw] = e;
    }
}

// ---------------- launch ----------------
extern "C" void kernel_launch(void* const* d_in, const int* in_sizes, int n_in,
                              void* d_out, int out_size) {
    const int*   atom_type = (const int*)d_in[0];
    const float* atom_pos  = (const float*)d_in[1];
    const int*   edge_src  = (const int*)d_in[2];
    const int*   edge_dst  = (const int*)d_in[3];
    const float* shift     = (const float*)d_in[4];
    const float* cell      = (const float*)d_in[5];
    const int*   image_idx = (const int*)d_in[6];
    const float* w_lin_in  = (const float*)d_in[7];
    const float* mw1       = (const float*)d_in[8];
    const float* mb1       = (const float*)d_in[9];
    const float* mw2       = (const float*)d_in[10];
    const float* wss       = (const float*)d_in[11];
    const float* wsv       = (const float*)d_in[12];
    const float* wgt       = (const float*)d_in[13];
    const float* wl1       = (const float*)d_in[14];
    const float* wl2       = (const float*)d_in[15];
    int N = in_sizes[0];
    int E = in_sizes[2];
    float* out = (float*)d_out;

    int nEdgeBlk = (E + 255) / 256;
    int nTabBlk  = NLAYERS * (NTAB / ENT);
    int nInitBlk = (N * 192 + 255) / 256;

    k_mega<<<nEdgeBlk + nTabBlk + nInitBlk, 256>>>(
        atom_pos, edge_src, edge_dst, shift, cell, image_idx,
        atom_type, w_lin_in, mw1, mb1, mw2, E, N, nEdgeBlk, nTabBlk);
    k_scan<<<1, 1024>>>(N);
    k_scatter<<<(E + 255) / 256, 256>>>(edge_dst, E, N);
    // layer 0 (specialized: v = 0)
    k_aggregate0<<<(N + 3) / 4, 256>>>(N);
    k_node<<<(N + 31) / 32, 256>>>(0, N, wss, wsv, wgt);
    for (int L = 1; L < NLAYERS; ++L) {
        k_aggregate<<<(N + 3) / 4, 256>>>(L, N);
        k_node<<<(N + 31) / 32, 256>>>(L, N, wss, wsv, wgt);
    }
    k_energy<<<(N + 7) / 8, 256>>>(N, wl1, wl2, out);
}

// round 17
// speedup vs baseline: 1.4337x; 1.2518x over previous
#include <cuda_runtime.h>
#include <cuda_fp16.h>
#include <math.h>

#define MAXN 16384
#define MAXE 524288
#define NTAB 4096
#define RMAXF 5.0f
#define NLAYERS 3
#define ENT 16
#define JT 16

// ---------------- static scratch (no allocation allowed) ----------------
__device__ uint4     g_ev[MAXE];        // unsorted: {yx h2, yy h2, yz h2, (ty<<26)|(src<<12)|i0}
__device__ uint4     g_rec[MAXE];       // dst-sorted records (same format)
__device__ int       g_hist[MAXN];      // zeroed by k_scatter for next replay
__device__ int       g_cur[MAXN];
__device__ int       g_off[MAXN + 1];
// nearest-entry half tables per lane: vals paths1-4 (16B), val path5 (4B)
__device__ uint4     g_tV[NLAYERS * NTAB * 32];
__device__ unsigned  g_t5[NLAYERS * NTAB * 32];
__device__ float     g_s[MAXN * 64];
__device__ float     g_v[MAXN * 192];   // layout [n][3][64]
__device__ float     g_as[MAXN * 64];
__device__ float     g_av[MAXN * 192];
__device__ uint4     g_feat[MAXN * 32]; // per lane: {s h2, vx h2, vy h2, vz h2}
__device__ uint4     g_s0tab[32];       // per lane: s-half2 for atom types 0..3

// ================= mega kernel: edge_pre | table build | init =================
__global__ void k_mega(const float* __restrict__ pos,
                       const int* __restrict__ esrc,
                       const int* __restrict__ edst,
                       const float* __restrict__ shift,
                       const float* __restrict__ cell,
                       const int* __restrict__ img,
                       const int* __restrict__ atom_type,
                       const float* __restrict__ w_lin_in,
                       const float* __restrict__ mw1,
                       const float* __restrict__ mb1,
                       const float* __restrict__ mw2,
                       int E, int N, int nEdgeBlk, int nTabBlk) {
    __shared__ float sh_h[ENT * 64];   // 4KB  (table branch)
    __shared__ float sh_w[JT * 320];   // 20KB (table branch)
    int b = blockIdx.x;
    int tid = threadIdx.x;

    if (b < nEdgeBlk) {
        // ---- edge preprocess ----
        int e = b * 256 + tid;
        if (e >= E) return;
        int s = esrc[e], d = edst[e];
        float vx = pos[d * 3 + 0] - pos[s * 3 + 0];
        float vy = pos[d * 3 + 1] - pos[s * 3 + 1];
        float vz = pos[d * 3 + 2] - pos[s * 3 + 2];
        float s0 = shift[e * 3 + 0], s1 = shift[e * 3 + 1], s2 = shift[e * 3 + 2];
        const float* Cm = cell + img[s] * 9;
        vx += s0 * Cm[0] + s1 * Cm[3] + s2 * Cm[6];
        vy += s0 * Cm[1] + s1 * Cm[4] + s2 * Cm[7];
        vz += s0 * Cm[2] + s1 * Cm[5] + s2 * Cm[8];
        float r = sqrtf(vx * vx + vy * vy + vz * vz);
        uint4 rec;
        if (r < RMAXF) {
            float inv = 1.7320508075688772f / fmaxf(r, 1e-9f);  // sqrt3 * unit
            __half2 hx = __half2half2(__float2half_rn(vx * inv));
            __half2 hy = __half2half2(__float2half_rn(vy * inv));
            __half2 hz = __half2half2(__float2half_rn(vz * inv));
            int i0 = __float2int_rn(r * ((float)(NTAB - 1) / RMAXF));
            if (i0 > NTAB - 1) i0 = NTAB - 1;
            unsigned ty = (unsigned)atom_type[s];
            rec.x = *(unsigned*)&hx; rec.y = *(unsigned*)&hy;
            rec.z = *(unsigned*)&hz;
            rec.w = (ty << 26) | ((unsigned)s << 12) | (unsigned)i0;
            atomicAdd(&g_hist[d], 1);
        } else {
            rec.x = rec.y = rec.z = 0;
            rec.w = 0xFFFFFFFFu;   // filtered marker
        }
        g_ev[e] = rec;
    } else if (b < nEdgeBlk + nTabBlk) {
        // ---- fused table build: h in-block, GEMM, pack ----
        int tb = b - nEdgeBlk;
        int L = tb / (NTAB / ENT);
        int e_blk = (tb % (NTAB / ENT)) * ENT;
        for (int i = tid; i < ENT * 64; i += 256) {
            int el = i >> 6, t = i & 63;
            int entry = e_blk + el;
            float r = (float)entry * (RMAXF / (float)(NTAB - 1));
            float rs = fmaxf(r, 1e-9f);
            float x = r / RMAXF;
            float x2 = x * x;
            float x6 = x2 * x2 * x2;
            float fc = 1.f - 28.f * x6 + 48.f * x6 * x - 21.f * x6 * x2;
            if (x >= 1.f) fc = 0.f;
            float cscale = sqrtf(2.f / RMAXF) * fc / rs;
            float arg = 3.14159265358979323846f * rs / RMAXF;
            float h = mb1[L * 64 + t];
#pragma unroll
            for (int j = 0; j < 8; j++)
                h += cscale * sinf((float)(j + 1) * arg) * mw1[(L * 8 + j) * 64 + t];
            sh_h[i] = h / (1.f + expf(-h));  // silu
        }

        int c = tid & 63;
        int eg = tid >> 6;
        float acc[4][5];
#pragma unroll
        for (int q = 0; q < 4; q++)
#pragma unroll
            for (int k = 0; k < 5; k++) acc[q][k] = 0.f;

        for (int j0 = 0; j0 < 64; j0 += JT) {
            __syncthreads();
            const float* wsrc = mw2 + ((size_t)L * 64 + j0) * 320;
            for (int i = tid; i < JT * 320; i += 256) sh_w[i] = wsrc[i];
            __syncthreads();
#pragma unroll
            for (int j = 0; j < JT; j++) {
                float w0 = sh_w[j * 320 + 0 * 64 + c];
                float w1 = sh_w[j * 320 + 1 * 64 + c];
                float w2 = sh_w[j * 320 + 2 * 64 + c];
                float w3 = sh_w[j * 320 + 3 * 64 + c];
                float w4 = sh_w[j * 320 + 4 * 64 + c];
#pragma unroll
                for (int q = 0; q < 4; q++) {
                    float hj = sh_h[(eg * 4 + q) * 64 + j0 + j];
                    acc[q][0] += hj * w0;
                    acc[q][1] += hj * w1;
                    acc[q][2] += hj * w2;
                    acc[q][3] += hj * w3;
                    acc[q][4] += hj * w4;
                }
            }
        }
        const float ISD = 0.17677669529663687f;          // 1/sqrt(32)
        const float SC[5] = {ISD, ISD * 0.57735026918962576f, ISD, ISD,
                             ISD * 0.70710678118654752f};
        __syncthreads();
#pragma unroll
        for (int q = 0; q < 4; q++)
#pragma unroll
            for (int k = 0; k < 5; k++)
                sh_w[(eg * 4 + q) * 320 + k * 64 + c] = acc[q][k] * SC[k];
        __syncthreads();
        for (int u = tid; u < ENT * 32; u += 256) {
            int el = u >> 5, lane = u & 31, cc = lane * 2;
            const float* row = sh_w + el * 320;
            __half2 p1 = __floats2half2_rn(row[0 * 64 + cc], row[0 * 64 + cc + 1]);
            __half2 p2 = __floats2half2_rn(row[1 * 64 + cc], row[1 * 64 + cc + 1]);
            __half2 p3 = __floats2half2_rn(row[2 * 64 + cc], row[2 * 64 + cc + 1]);
            __half2 p4 = __floats2half2_rn(row[3 * 64 + cc], row[3 * 64 + cc + 1]);
            __half2 p5 = __floats2half2_rn(row[4 * 64 + cc], row[4 * 64 + cc + 1]);
            size_t base = ((size_t)L * NTAB + e_blk + el) * 32 + lane;
            g_tV[base] = make_uint4(*(unsigned*)&p1, *(unsigned*)&p2,
                                    *(unsigned*)&p3, *(unsigned*)&p4);
            g_t5[base] = *(unsigned*)&p5;
        }
    } else {
        // ---- node feature init ----
        int i = (b - nEdgeBlk - nTabBlk) * 256 + tid;
        if (i < N * 192) g_v[i] = 0.f;
        if (i < N * 64) {
            int n = i >> 6, cc = i & 63;
            g_s[i] = w_lin_in[atom_type[n] * 64 + cc];
        }
        if (i < N * 32) {
            int n = i >> 5, l = i & 31;
            int t = atom_type[n];
            __half2 s2 = __floats2half2_rn(w_lin_in[t * 64 + 2 * l],
                                           w_lin_in[t * 64 + 2 * l + 1]);
            __half2 z2 = __floats2half2_rn(0.f, 0.f);
            uint4 f4;
            f4.x = *(unsigned*)&s2; f4.y = *(unsigned*)&z2;
            f4.z = *(unsigned*)&z2; f4.w = *(unsigned*)&z2;
            g_feat[i] = f4;
        }
        if (i < 32) {
            unsigned pk[4];
#pragma unroll
            for (int t = 0; t < 4; t++) {
                __half2 h = __floats2half2_rn(w_lin_in[t * 64 + 2 * i],
                                              w_lin_in[t * 64 + 2 * i + 1]);
                pk[t] = *(unsigned*)&h;
            }
            g_s0tab[i] = make_uint4(pk[0], pk[1], pk[2], pk[3]);
        }
    }
}

// ---------------- single-block exclusive scan ----------------
__global__ void k_scan(int N) {
    __shared__ int sm[1024];
    int tid = threadIdx.x;
    int per = (N + 1023) >> 10;
    int st = tid * per;
    int s = 0;
    for (int i = 0; i < per; i++) { int idx = st + i; if (idx < N) s += g_hist[idx]; }
    sm[tid] = s;
    __syncthreads();
    for (int d = 1; d < 1024; d <<= 1) {
        int v = (tid >= d) ? sm[tid - d] : 0;
        __syncthreads();
        sm[tid] += v;
        __syncthreads();
    }
    int pre = tid ? sm[tid - 1] : 0;
    for (int i = 0; i < per; i++) {
        int idx = st + i;
        if (idx < N) { g_off[idx] = pre; g_cur[idx] = pre; pre += g_hist[idx]; }
    }
    if (tid == 0) g_off[N] = sm[1023];
}

// -------- scatter into dst-sorted order; also re-zero g_hist for next replay --------
__global__ void k_scatter(const int* __restrict__ edst, int E, int N) {
    int e = blockIdx.x * blockDim.x + threadIdx.x;
    if (e < N) g_hist[e] = 0;
    if (e >= E) return;
    uint4 rec = g_ev[e];
    if (rec.w == 0xFFFFFFFFu) return;   // filtered
    int d = edst[e];
    int p = atomicAdd(&g_cur[d], 1);
    g_rec[p] = rec;
}

#define H2(u) (*(__half2*)&(u))

// per-edge message math in half2; accumulation folded into the fma chains
__device__ __forceinline__ void edge_acc(uint4 rc, uint4 qv, unsigned q5, uint4 ft,
                                         __half2& hS, __half2& hX,
                                         __half2& hY, __half2& hZ) {
    __half2 w1 = H2(qv.x), w2 = H2(qv.y), w3 = H2(qv.z), w4 = H2(qv.w), w5 = H2(q5);
    __half2 s01 = H2(ft.x), vx = H2(ft.y), vy = H2(ft.z), vz = H2(ft.w);
    __half2 yx2 = H2(rc.x), yy2 = H2(rc.y), yz2 = H2(rc.z);
    __half2 vd = __hfma2(vz, yz2, __hfma2(vy, yy2, __hmul2(vx, yx2)));
    hS = __hfma2(w1, s01, __hfma2(w2, vd, hS));
    __half2 t3 = __hmul2(w3, s01);
    __half2 cxh = __hfma2(__hneg2(vz), yy2, __hmul2(vy, yz2));
    __half2 cyh = __hfma2(__hneg2(vx), yz2, __hmul2(vz, yx2));
    __half2 czh = __hfma2(__hneg2(vy), yx2, __hmul2(vx, yy2));
    hX = __hfma2(w5, cxh, __hfma2(w4, vx, __hfma2(t3, yx2, hX)));
    hY = __hfma2(w5, cyh, __hfma2(w4, vy, __hfma2(t3, yy2, hY)));
    hZ = __hfma2(w5, czh, __hfma2(w4, vz, __hfma2(t3, yz2, hZ)));
}

// layer-0 message: v=0, s from type table -> only paths 1 and 3 survive
__device__ __forceinline__ void edge_acc0(uint4 rc, uint4 qv, uint4 st,
                                          __half2& hS, __half2& hX,
                                          __half2& hY, __half2& hZ) {
    unsigned ty = rc.w >> 26;
    unsigned su = (ty & 2u) ? ((ty & 1u) ? st.w : st.z)
                            : ((ty & 1u) ? st.y : st.x);
    __half2 s01 = H2(su);
    __half2 w1 = H2(qv.x), w3 = H2(qv.z);
    __half2 yx2 = H2(rc.x), yy2 = H2(rc.y), yz2 = H2(rc.z);
    hS = __hfma2(w1, s01, hS);
    __half2 t3 = __hmul2(w3, s01);
    hX = __hfma2(t3, yx2, hX);
    hY = __hfma2(t3, yy2, hY);
    hZ = __hfma2(t3, yz2, hZ);
}

// ------- general-layer aggregate (L=1,2): copy-free double-buffered pipeline -------
__global__ void __launch_bounds__(256, 4) k_aggregate(int L, int N) {
    __shared__ float red[4][8][32];
    int tid = threadIdx.x;
    int lane = tid & 31;
    int warpInBlk = tid >> 5;
    int atomInBlk = warpInBlk >> 1;
    int half = warpInBlk & 1;
    int atom = blockIdx.x * 4 + atomInBlk;
    int valid = atom < N;
    int o0 = valid ? g_off[atom] : 0;
    int o1 = valid ? g_off[atom + 1] : 0;
    int c0 = lane << 1;
    float aS0 = 0, aS1 = 0, aX0 = 0, aX1 = 0, aY0 = 0, aY1 = 0, aZ0 = 0, aZ1 = 0;
    const uint4* tV = g_tV + (size_t)L * NTAB * 32;
    const unsigned* t5 = g_t5 + (size_t)L * NTAB * 32;
    const __half2 hz2 = __floats2half2_rn(0.f, 0.f);

    int p = o0 + half;
    int m = o1 - p; m = m > 0 ? (m + 1) >> 1 : 0;

    if (m > 0) {
        uint4 recA = g_rec[p];
        int ibA = (int)(recA.w & 0xFFFu) * 32 + lane;
        uint4 qvA = tV[ibA]; unsigned q5A = t5[ibA];
        uint4 ftA = g_feat[(int)((recA.w >> 12) & 0x3FFFu) * 32 + lane];

        uint4 recB, qvB, ftB; unsigned q5B = 0;
        if (m > 1) {
            recB = g_rec[p + 2];
            int ibB = (int)(recB.w & 0xFFFu) * 32 + lane;
            qvB = tV[ibB]; q5B = t5[ibB];
            ftB = g_feat[(int)((recB.w >> 12) & 0x3FFFu) * 32 + lane];
        }
        uint4 recQ0 = g_rec[p + 4];
        uint4 recQ1 = g_rec[p + 6];

        int k = 0;
        for (; k + 3 < m; k += 2) {
            __half2 hS = hz2, hX = hz2, hY = hz2, hZ = hz2;
            edge_acc(recA, qvA, q5A, ftA, hS, hX, hY, hZ);
            recA = recQ0;
            {
                int ib = (int)(recA.w & 0xFFFu) * 32 + lane;
                qvA = tV[ib]; q5A = t5[ib];
                ftA = g_feat[(int)((recA.w >> 12) & 0x3FFFu) * 32 + lane];
            }
            recQ0 = g_rec[p + 2 * (k + 4)];
            edge_acc(recB, qvB, q5B, ftB, hS, hX, hY, hZ);
            recB = recQ1;
            {
                int ib = (int)(recB.w & 0xFFFu) * 32 + lane;
                qvB = tV[ib]; q5B = t5[ib];
                ftB = g_feat[(int)((recB.w >> 12) & 0x3FFFu) * 32 + lane];
            }
            recQ1 = g_rec[p + 2 * (k + 5)];
            float2 f;
            f = __half22float2(hS); aS0 += f.x; aS1 += f.y;
            f = __half22float2(hX); aX0 += f.x; aX1 += f.y;
            f = __half22float2(hY); aY0 += f.x; aY1 += f.y;
            f = __half22float2(hZ); aZ0 += f.x; aZ1 += f.y;
        }
        {
            __half2 hS = hz2, hX = hz2, hY = hz2, hZ = hz2;
            if (k < m)     edge_acc(recA, qvA, q5A, ftA, hS, hX, hY, hZ);
            if (k + 1 < m) edge_acc(recB, qvB, q5B, ftB, hS, hX, hY, hZ);
            if (k + 2 < m) {
                int ib = (int)(recQ0.w & 0xFFFu) * 32 + lane;
                uint4 qv = tV[ib];
                unsigned q5v = t5[ib];
                uint4 ft = g_feat[(int)((recQ0.w >> 12) & 0x3FFFu) * 32 + lane];
                edge_acc(recQ0, qv, q5v, ft, hS, hX, hY, hZ);
            }
            float2 f;
            f = __half22float2(hS); aS0 += f.x; aS1 += f.y;
            f = __half22float2(hX); aX0 += f.x; aX1 += f.y;
            f = __half22float2(hY); aY0 += f.x; aY1 += f.y;
            f = __half22float2(hZ); aZ0 += f.x; aZ1 += f.y;
        }
    }

    if (half) {
        red[atomInBlk][0][lane] = aS0; red[atomInBlk][1][lane] = aS1;
        red[atomInBlk][2][lane] = aX0; red[atomInBlk][3][lane] = aX1;
        red[atomInBlk][4][lane] = aY0; red[atomInBlk][5][lane] = aY1;
        red[atomInBlk][6][lane] = aZ0; red[atomInBlk][7][lane] = aZ1;
    }
    __syncthreads();
    if (!half && valid) {
        aS0 += red[atomInBlk][0][lane]; aS1 += red[atomInBlk][1][lane];
        aX0 += red[atomInBlk][2][lane]; aX1 += red[atomInBlk][3][lane];
        aY0 += red[atomInBlk][4][lane]; aY1 += red[atomInBlk][5][lane];
        aZ0 += red[atomInBlk][6][lane]; aZ1 += red[atomInBlk][7][lane];
        *(float2*)(g_as + atom * 64 + c0) = make_float2(aS0, aS1);
        float* ov = g_av + atom * 192 + c0;
        *(float2*)(ov) = make_float2(aX0, aX1);
        *(float2*)(ov + 64) = make_float2(aY0, aY1);
        *(float2*)(ov + 128) = make_float2(aZ0, aZ1);
    }
}

// ------- layer-0 aggregate: no feature gather, type-indexed s, 2 loads/edge -------
__global__ void __launch_bounds__(256, 4) k_aggregate0(int N) {
    __shared__ float red[4][8][32];
    int tid = threadIdx.x;
    int lane = tid & 31;
    int warpInBlk = tid >> 5;
    int atomInBlk = warpInBlk >> 1;
    int half = warpInBlk & 1;
    int atom = blockIdx.x * 4 + atomInBlk;
    int valid = atom < N;
    int o0 = valid ? g_off[atom] : 0;
    int o1 = valid ? g_off[atom + 1] : 0;
    int c0 = lane << 1;
    float aS0 = 0, aS1 = 0, aX0 = 0, aX1 = 0, aY0 = 0, aY1 = 0, aZ0 = 0, aZ1 = 0;
    const uint4* tV = g_tV;
    const uint4 st = g_s0tab[lane];
    const __half2 hz2 = __floats2half2_rn(0.f, 0.f);

    int p = o0 + half;
    int m = o1 - p; m = m > 0 ? (m + 1) >> 1 : 0;

    if (m > 0) {
        uint4 recA = g_rec[p];
        uint4 qvA = tV[(int)(recA.w & 0xFFFu) * 32 + lane];
        uint4 recB, qvB;
        if (m > 1) {
            recB = g_rec[p + 2];
            qvB = tV[(int)(recB.w & 0xFFFu) * 32 + lane];
        }
        uint4 recQ0 = g_rec[p + 4];
        uint4 recQ1 = g_rec[p + 6];

        int k = 0;
        for (; k + 3 < m; k += 2) {
            __half2 hS = hz2, hX = hz2, hY = hz2, hZ = hz2;
            edge_acc0(recA, qvA, st, hS, hX, hY, hZ);
            recA = recQ0;
            qvA = tV[(int)(recA.w & 0xFFFu) * 32 + lane];
            recQ0 = g_rec[p + 2 * (k + 4)];
            edge_acc0(recB, qvB, st, hS, hX, hY, hZ);
            recB = recQ1;
            qvB = tV[(int)(recB.w & 0xFFFu) * 32 + lane];
            recQ1 = g_rec[p + 2 * (k + 5)];
            float2 f;
            f = __half22float2(hS); aS0 += f.x; aS1 += f.y;
            f = __half22float2(hX); aX0 += f.x; aX1 += f.y;
            f = __half22float2(hY); aY0 += f.x; aY1 += f.y;
            f = __half22float2(hZ); aZ0 += f.x; aZ1 += f.y;
        }
        {
            __half2 hS = hz2, hX = hz2, hY = hz2, hZ = hz2;
            if (k < m)     edge_acc0(recA, qvA, st, hS, hX, hY, hZ);
            if (k + 1 < m) edge_acc0(recB, qvB, st, hS, hX, hY, hZ);
            if (k + 2 < m) {
                uint4 qv = tV[(int)(recQ0.w & 0xFFFu) * 32 + lane];
                edge_acc0(recQ0, qv, st, hS, hX, hY, hZ);
            }
            float2 f;
            f = __half22float2(hS); aS0 += f.x; aS1 += f.y;
            f = __half22float2(hX); aX0 += f.x; aX1 += f.y;
            f = __half22float2(hY); aY0 += f.x; aY1 += f.y;
            f = __half22float2(hZ); aZ0 += f.x; aZ1 += f.y;
        }
    }

    if (half) {
        red[atomInBlk][0][lane] = aS0; red[atomInBlk][1][lane] = aS1;
        red[atomInBlk][2][lane] = aX0; red[atomInBlk][3][lane] = aX1;
        red[atomInBlk][4][lane] = aY0; red[atomInBlk][5][lane] = aY1;
        red[atomInBlk][6][lane] = aZ0; red[atomInBlk][7][lane] = aZ1;
    }
    __syncthreads();
    if (!half && valid) {
        aS0 += red[atomInBlk][0][lane]; aS1 += red[atomInBlk][1][lane];
        aX0 += red[atomInBlk][2][lane]; aX1 += red[atomInBlk][3][lane];
        aY0 += red[atomInBlk][4][lane]; aY1 += red[atomInBlk][5][lane];
        aZ0 += red[atomInBlk][6][lane]; aZ1 += red[atomInBlk][7][lane];
        *(float2*)(g_as + atom * 64 + c0) = make_float2(aS0, aS1);
        float* ov = g_av + atom * 192 + c0;
        *(float2*)(ov) = make_float2(aX0, aX1);
        *(float2*)(ov + 64) = make_float2(aY0, aY1);
        *(float2*)(ov + 128) = make_float2(aZ0, aZ1);
    }
}

__device__ __forceinline__ __half2 splat_h2(float v) {
    return __half2half2(__float2half_rn(v));
}

// ---- node self-interaction + resnet (+feat mirror); half2 smem matvec;
//      4 atoms per warp; fused energy head on last layer ----
__global__ void k_node(int L, int N, const float* __restrict__ wss,
                       const float* __restrict__ wsv,
                       const float* __restrict__ wgt,
                       const float* __restrict__ wl1,
                       const float* __restrict__ wl2,
                       float* __restrict__ out) {
    __shared__ __half2 sWg[64 * 32];   // 8KB
    __shared__ __half2 sWs[64 * 32];   // 8KB
    __shared__ __half2 sWv[64 * 32];   // 8KB
    __shared__ __half2 sIn[8][256];    // 8KB: per warp {a[64], ax[64], ay[64], az[64]} splats
    __shared__ float   sWe[64];        // fused energy weights
    const float* ps = wss + (size_t)L * 4096;
    const float* pv = wsv + (size_t)L * 4096;
    const float* pg = wgt + (size_t)L * 4096;
    int tid = threadIdx.x;
    for (int i = tid; i < 64 * 32; i += 256) {
        int j = i >> 5, l = i & 31;
        sWg[i] = __floats2half2_rn(pg[j * 64 + 2 * l], pg[j * 64 + 2 * l + 1]);
        sWs[i] = __floats2half2_rn(ps[j * 64 + 2 * l], ps[j * 64 + 2 * l + 1]);
        sWv[i] = __floats2half2_rn(pv[j * 64 + 2 * l], pv[j * 64 + 2 * l + 1]);
    }
    int lastL = (L == NLAYERS - 1);
    if (lastL && tid < 64) {
        float w = 0.f;
#pragma unroll
        for (int k = 0; k < 16; k++) w += wl1[tid * 16 + k] * wl2[k];
        sWe[tid] = w;
    }
    __syncthreads();
    int lane = tid & 31;
    int warp = tid >> 5;
    int c0 = lane << 1;
    __half2* S = sIn[warp];
    const __half2 hz2 = __floats2half2_rn(0.f, 0.f);
    int baseAtom = blockIdx.x * 32 + warp * 4;
    for (int a = 0; a < 4; a++) {
        int gw = baseAtom + a;
        if (gw >= N) break;
        float2 aa = *(const float2*)(g_as + gw * 64 + c0);
        const float* avp = g_av + gw * 192 + c0;
        float2 ax = *(const float2*)(avp);
        float2 ay = *(const float2*)(avp + 64);
        float2 az = *(const float2*)(avp + 128);
        // stage splats
        S[c0] = splat_h2(aa.x);       S[c0 + 1] = splat_h2(aa.y);
        S[64 + c0] = splat_h2(ax.x);  S[64 + c0 + 1] = splat_h2(ax.y);
        S[128 + c0] = splat_h2(ay.x); S[128 + c0 + 1] = splat_h2(ay.y);
        S[192 + c0] = splat_h2(az.x); S[192 + c0 + 1] = splat_h2(az.y);
        __syncwarp();
        float gs0 = 0, gs1 = 0, t0 = 0, t1 = 0;
        float vx0 = 0, vx1 = 0, vy0 = 0, vy1 = 0, vz0 = 0, vz1 = 0;
        for (int j0 = 0; j0 < 64; j0 += 16) {
            __half2 aG = hz2, aT = hz2, aX = hz2, aY = hz2, aZ = hz2;
#pragma unroll
            for (int j = 0; j < 16; j++) {
                int jj = j0 + j;
                __half2 aj = S[jj];
                __half2 jx = S[64 + jj];
                __half2 jy = S[128 + jj];
                __half2 jz = S[192 + jj];
                __half2 wg2 = sWg[jj * 32 + lane];
                __half2 ws2 = sWs[jj * 32 + lane];
                __half2 wv2 = sWv[jj * 32 + lane];
                aG = __hfma2(aj, wg2, aG);
                aT = __hfma2(aj, ws2, aT);
                aX = __hfma2(jx, wv2, aX);
                aY = __hfma2(jy, wv2, aY);
                aZ = __hfma2(jz, wv2, aZ);
            }
            float2 f;
            f = __half22float2(aG); gs0 += f.x; gs1 += f.y;
            f = __half22float2(aT); t0 += f.x;  t1 += f.y;
            f = __half22float2(aX); vx0 += f.x; vx1 += f.y;
            f = __half22float2(aY); vy0 += f.x; vy1 += f.y;
            f = __half22float2(aZ); vz0 += f.x; vz1 += f.y;
        }
        float g0 = 1.f / (1.f + expf(-gs0));
        float g1 = 1.f / (1.f + expf(-gs1));
        float si0 = t0 / (1.f + expf(-t0));
        float si1 = t1 / (1.f + expf(-t1));
        float* sp = g_s + gw * 64 + c0;
        float2 sv = *(float2*)sp;
        sv.x += si0; sv.y += si1;
        *(float2*)sp = sv;
        float* vp = g_v + gw * 192 + c0;
        float2 v1, v2, v3;
        v1 = *(float2*)(vp);       v1.x += vx0 * g0; v1.y += vx1 * g1; *(float2*)(vp) = v1;
        v2 = *(float2*)(vp + 64);  v2.x += vy0 * g0; v2.y += vy1 * g1; *(float2*)(vp + 64) = v2;
        v3 = *(float2*)(vp + 128); v3.x += vz0 * g0; v3.y += vz1 * g1; *(float2*)(vp + 128) = v3;
        if (!lastL) {
            __half2 hs = __floats2half2_rn(sv.x, sv.y);
            __half2 h1 = __floats2half2_rn(v1.x, v1.y);
            __half2 h2 = __floats2half2_rn(v2.x, v2.y);
            __half2 h3 = __floats2half2_rn(v3.x, v3.y);
            uint4 f4;
            f4.x = *(unsigned*)&hs; f4.y = *(unsigned*)&h1;
            f4.z = *(unsigned*)&h2; f4.w = *(unsigned*)&h3;
            g_feat[gw * 32 + lane] = f4;
        } else {
            // fused energy head: e = dot(s, wl1@wl2)
            float e = sv.x * sWe[c0] + sv.y * sWe[c0 + 1];
#pragma unroll
            for (int d = 16; d >= 1; d >>= 1)
                e += __shfl_down_sync(0xffffffffu, e, d);
            if (lane == 0) out[gw] = e;
        }
        __syncwarp();
    }
}

// ---------------- launch ----------------
extern "C" void kernel_launch(void* const* d_in, const int* in_sizes, int n_in,
                              void* d_out, int out_size) {
    const int*   atom_type = (const int*)d_in[0];
    const float* atom_pos  = (const float*)d_in[1];
    const int*   edge_src  = (const int*)d_in[2];
    const int*   edge_dst  = (const int*)d_in[3];
    const float* shift     = (const float*)d_in[4];
    const float* cell      = (const float*)d_in[5];
    const int*   image_idx = (const int*)d_in[6];
    const float* w_lin_in  = (const float*)d_in[7];
    const float* mw1       = (const float*)d_in[8];
    const float* mb1       = (const float*)d_in[9];
    const float* mw2       = (const float*)d_in[10];
    const float* wss       = (const float*)d_in[11];
    const float* wsv       = (const float*)d_in[12];
    const float* wgt       = (const float*)d_in[13];
    const float* wl1       = (const float*)d_in[14];
    const float* wl2       = (const float*)d_in[15];
    int N = in_sizes[0];
    int E = in_sizes[2];
    float* out = (float*)d_out;

    int nEdgeBlk = (E + 255) / 256;
    int nTabBlk  = NLAYERS * (NTAB / ENT);
    int nInitBlk = (N * 192 + 255) / 256;

    k_mega<<<nEdgeBlk + nTabBlk + nInitBlk, 256>>>(
        atom_pos, edge_src, edge_dst, shift, cell, image_idx,
        atom_type, w_lin_in, mw1, mb1, mw2, E, N, nEdgeBlk, nTabBlk);
    k_scan<<<1, 1024>>>(N);
    k_scatter<<<(E + 255) / 256, 256>>>(edge_dst, E, N);
    // layer 0 (specialized: v = 0)
    k_aggregate0<<<(N + 3) / 4, 256>>>(N);
    k_node<<<(N + 31) / 32, 256>>>(0, N, wss, wsv, wgt, wl1, wl2, out);
    for (int L = 1; L < NLAYERS; ++L) {
        k_aggregate<<<(N + 3) / 4, 256>>>(L, N);
        k_node<<<(N + 31) / 32, 256>>>(L, N, wss, wsv, wgt, wl1, wl2, out);
    }
    k_energy_removed:;
}